// round 1
// baseline (speedup 1.0000x reference)
#include <cuda_runtime.h>

#define BB 64
#define NQv 1024
#define LLv 128
#define EEv 8192

// ---------------- scratch (static device globals; no allocations) ----------
__device__ float g_h[BB * NQv * LLv];      // node states
__device__ float g_A[BB * NQv * LLv];      // h @ W1a^T + b1   (round 1)
__device__ float g_Bv[BB * NQv * LLv];     // h @ W1b^T        (round 1)
__device__ float g_magg[BB * NQv * LLv];   // aggregated messages
__device__ float g_base[BB * LLv];         // round-0 collapsed layer-1
__device__ float g_w1a[2][LLv][LLv];       // packed e_w1[:, :, 0:128]
__device__ float g_w1b[2][LLv][LLv];       // packed e_w1[:, :, 128:256]
__device__ float g_w1c[2][LLv];            // packed e_w1[:, :, 256]
__device__ int   g_is64;                   // edge_index dtype flag

__device__ __forceinline__ float dot4(float4 x, float4 w, float acc) {
    acc = fmaf(x.x, w.x, acc);
    acc = fmaf(x.y, w.y, acc);
    acc = fmaf(x.z, w.z, acc);
    acc = fmaf(x.w, w.w, acc);
    return acc;
}

// ---------------- small setup kernels ---------------------------------------
__global__ void detect_idx_kernel(const void* __restrict__ ei) {
    // If data is really int64, every entry is in [0, NQ). If it is int32,
    // interpreting pairs as int64 produces values >= 2^32 almost surely.
    const long long* p = (const long long*)ei;
    int ok = 1;
    for (int i = 0; i < 64; i++) {
        long long v = p[i];
        if (v < 0 || v >= NQv) { ok = 0; break; }
    }
    g_is64 = ok;
}

__global__ void pack_w1_kernel(const float* __restrict__ ew1) {
    int idx = blockIdx.x * blockDim.x + threadIdx.x;   // over 2*128*257
    if (idx >= 2 * LLv * 257) return;
    int k   = idx / (LLv * 257);
    int rem = idx % (LLv * 257);
    int c = rem / 257, j = rem % 257;
    float v = ew1[idx];
    if (j < 128)      g_w1a[k][c][j]       = v;
    else if (j < 256) g_w1b[k][c][j - 128] = v;
    else              g_w1c[k][c]          = v;
}

__global__ void init_h_kernel(const float* __restrict__ z0) {
    int i = blockIdx.x * 256 + threadIdx.x;   // over B*NQ*L = 2^23
    int l = i & 127;
    int b = i >> 17;                          // NQ*L = 131072 = 2^17
    g_h[i] = z0[b * LLv + l];
}

__global__ void zero_magg_kernel() {
    int i = blockIdx.x * 256 + threadIdx.x;   // over B*NQ*L/4
    ((float4*)g_magg)[i] = make_float4(0.f, 0.f, 0.f, 0.f);
}

// round-0 collapsed layer-1 base: base[b][l] = z0[b] . (W1a[l]+W1b[l]) + b1[l]
__global__ void base_kernel(const float* __restrict__ z0,
                            const float* __restrict__ eb1) {
    int b = blockIdx.x, l = threadIdx.x;   // 64 blocks x 128 threads
    __shared__ float zs[LLv];
    zs[l] = z0[b * LLv + l];
    __syncthreads();
    float acc = eb1[l];
#pragma unroll 4
    for (int j = 0; j < LLv; j++)
        acc = fmaf(zs[j], g_w1a[0][l][j] + g_w1b[0][l][j], acc);
    g_base[b * LLv + l] = acc;
}

// ---------------- round-1 per-node projections ------------------------------
// A[row] = h[row] @ W1a^T + b1 ; Bv[row] = h[row] @ W1b^T
__global__ __launch_bounds__(256) void proj_kernel(const float* __restrict__ eb1) {
    __shared__ __align__(16) float inp[64][LLv];   // 32 KB
    int r0 = blockIdx.x * 64, t = threadIdx.x;

    const float4* hp = (const float4*)(g_h + r0 * LLv);
    float4* ip = (float4*)&inp[0][0];
#pragma unroll
    for (int i = 0; i < 8; i++) ip[t + i * 256] = hp[t + i * 256];
    __syncthreads();

    int cl = t & 31, rg = t >> 5;   // 8 row-groups x 32 col-lanes

#pragma unroll 1
    for (int target = 0; target < 2; target++) {
        const float* W = (target == 0) ? &g_w1a[1][0][0] : &g_w1b[1][0][0];
        float acc[8][4];
#pragma unroll
        for (int j = 0; j < 8; j++)
#pragma unroll
            for (int cb = 0; cb < 4; cb++) acc[j][cb] = 0.f;

#pragma unroll 1
        for (int kk = 0; kk < LLv; kk += 4) {
            float4 w0 = *(const float4*)&W[(cl     ) * LLv + kk];
            float4 w1 = *(const float4*)&W[(cl + 32) * LLv + kk];
            float4 w2 = *(const float4*)&W[(cl + 64) * LLv + kk];
            float4 w3 = *(const float4*)&W[(cl + 96) * LLv + kk];
#pragma unroll
            for (int j = 0; j < 8; j++) {
                float4 x = *(const float4*)&inp[rg * 8 + j][kk];
                acc[j][0] = dot4(x, w0, acc[j][0]);
                acc[j][1] = dot4(x, w1, acc[j][1]);
                acc[j][2] = dot4(x, w2, acc[j][2]);
                acc[j][3] = dot4(x, w3, acc[j][3]);
            }
        }
        float* out = (target == 0) ? g_A : g_Bv;
#pragma unroll
        for (int cb = 0; cb < 4; cb++) {
            int c = cl + 32 * cb;
            float bias = (target == 0) ? eb1[c] : 0.f;
#pragma unroll
            for (int j = 0; j < 8; j++)
                out[(r0 + rg * 8 + j) * LLv + c] = acc[j][cb] + bias;
        }
    }
}

// ---------------- edge kernel: hidden -> layer2 -> scatter-add --------------
__global__ __launch_bounds__(256) void edge_kernel(
    const float* __restrict__ ew2, const float* __restrict__ eb2,
    const void* __restrict__ eidx, const float* __restrict__ eattr, int k)
{
    __shared__ __align__(16) float hid[64][LLv];   // 32 KB
    __shared__ int   src_s[64];
    __shared__ int   tgt_s[64];
    __shared__ float ea_s[64];

    int b = blockIdx.y, e0 = blockIdx.x * 64, t = threadIdx.x;

    if (t < 64) {
        if (g_is64) {
            const long long* p = (const long long*)eidx;
            src_s[t] = (int)p[e0 + t];
            tgt_s[t] = (int)p[EEv + e0 + t];
        } else {
            const int* p = (const int*)eidx;
            src_s[t] = p[e0 + t];
            tgt_s[t] = p[EEv + e0 + t];
        }
        ea_s[t] = eattr[e0 + t];
    }
    __syncthreads();

    // hidden = relu(pre),  pre = A[src] + B[tgt] + eattr*w1c   (k=0: base)
    if (k == 0) {
#pragma unroll 4
        for (int idx = t; idx < 64 * LLv; idx += 256) {
            int e = idx >> 7, l = idx & 127;
            float pre = g_base[b * LLv + l] + ea_s[e] * g_w1c[0][l];
            hid[e][l] = fmaxf(pre, 0.f);
        }
    } else {
        int nb = b * NQv;
#pragma unroll 4
        for (int idx = t; idx < 64 * LLv; idx += 256) {
            int e = idx >> 7, l = idx & 127;
            float pre = g_A[(nb + src_s[e]) * LLv + l]
                      + g_Bv[(nb + tgt_s[e]) * LLv + l]
                      + ea_s[e] * g_w1c[1][l];
            hid[e][l] = fmaxf(pre, 0.f);
        }
    }
    __syncthreads();

    // layer2: m[e][c] = hidden[e] . ew2[c] + eb2[c]; scatter-add to magg[src]
    int cl = t & 31, rg = t >> 5;
    float acc[8][4];
#pragma unroll
    for (int j = 0; j < 8; j++)
#pragma unroll
        for (int cb = 0; cb < 4; cb++) acc[j][cb] = 0.f;

#pragma unroll 1
    for (int kk = 0; kk < LLv; kk += 4) {
        float4 w0 = *(const float4*)&ew2[(cl     ) * LLv + kk];
        float4 w1 = *(const float4*)&ew2[(cl + 32) * LLv + kk];
        float4 w2 = *(const float4*)&ew2[(cl + 64) * LLv + kk];
        float4 w3 = *(const float4*)&ew2[(cl + 96) * LLv + kk];
#pragma unroll
        for (int j = 0; j < 8; j++) {
            float4 x = *(const float4*)&hid[rg * 8 + j][kk];
            acc[j][0] = dot4(x, w0, acc[j][0]);
            acc[j][1] = dot4(x, w1, acc[j][1]);
            acc[j][2] = dot4(x, w2, acc[j][2]);
            acc[j][3] = dot4(x, w3, acc[j][3]);
        }
    }

    int nb = b * NQv;
#pragma unroll
    for (int cb = 0; cb < 4; cb++) {
        int c = cl + 32 * cb;
        float bias = eb2[c];
#pragma unroll
        for (int j = 0; j < 8; j++) {
            int e = rg * 8 + j;
            atomicAdd(&g_magg[(nb + src_s[e]) * LLv + c], acc[j][cb] + bias);
        }
    }
}

// ---------------- node kernel: MLP + LayerNorm + residual (fused) -----------
__global__ __launch_bounds__(256) void node_kernel(
    const float* __restrict__ nw1, const float* __restrict__ nb1,
    const float* __restrict__ lng, const float* __restrict__ lnb,
    const float* __restrict__ nw2, const float* __restrict__ nb2)
{
    __shared__ __align__(16) float inp[32][256];   // [h | magg], 32 KB
    __shared__ __align__(16) float xs[32][LLv];    // 16 KB  (total = 48 KB)

    int b = blockIdx.y, q0 = blockIdx.x * 32, t = threadIdx.x;
    int rowbase = (b * NQv + q0) * LLv;

    const float4* hp = (const float4*)(g_h + rowbase);
    const float4* mp = (const float4*)(g_magg + rowbase);
#pragma unroll
    for (int i = 0; i < 4; i++) {
        int idx = t + i * 256;            // 0..1023 -> 32 rows x 32 float4
        int q = idx >> 5, j4 = idx & 31;
        ((float4*)&inp[q][0])[j4]   = hp[idx];
        ((float4*)&inp[q][128])[j4] = mp[idx];
    }
    __syncthreads();

    int cl = t & 31, rg = t >> 5;   // 8 row-groups x 4 rows, 32 col-lanes

    // ---- layer1: x = relu([h|magg] @ nw1^T + nb1) ----
    {
        float acc[4][4];
#pragma unroll
        for (int j = 0; j < 4; j++)
#pragma unroll
            for (int cb = 0; cb < 4; cb++) acc[j][cb] = 0.f;

#pragma unroll 1
        for (int kk = 0; kk < 256; kk += 4) {
            float4 w0 = *(const float4*)&nw1[(cl     ) * 256 + kk];
            float4 w1 = *(const float4*)&nw1[(cl + 32) * 256 + kk];
            float4 w2 = *(const float4*)&nw1[(cl + 64) * 256 + kk];
            float4 w3 = *(const float4*)&nw1[(cl + 96) * 256 + kk];
#pragma unroll
            for (int j = 0; j < 4; j++) {
                float4 x = *(const float4*)&inp[rg * 4 + j][kk];
                acc[j][0] = dot4(x, w0, acc[j][0]);
                acc[j][1] = dot4(x, w1, acc[j][1]);
                acc[j][2] = dot4(x, w2, acc[j][2]);
                acc[j][3] = dot4(x, w3, acc[j][3]);
            }
        }
#pragma unroll
        for (int cb = 0; cb < 4; cb++) {
            int c = cl + 32 * cb;
            float bi = nb1[c];
#pragma unroll
            for (int j = 0; j < 4; j++)
                xs[rg * 4 + j][c] = fmaxf(acc[j][cb] + bi, 0.f);
        }
    }
    __syncthreads();

    // ---- LayerNorm over L=128 (warp handles 4 rows) ----
    {
        int lane = t & 31, w = t >> 5;
#pragma unroll
        for (int j = 0; j < 4; j++) {
            int q = w * 4 + j;
            float v0 = xs[q][lane], v1 = xs[q][lane + 32];
            float v2 = xs[q][lane + 64], v3 = xs[q][lane + 96];
            float s = v0 + v1 + v2 + v3;
#pragma unroll
            for (int o = 16; o; o >>= 1) s += __shfl_xor_sync(0xffffffffu, s, o);
            float mu = s * (1.f / 128.f);
            float d0 = v0 - mu, d1 = v1 - mu, d2 = v2 - mu, d3 = v3 - mu;
            float s2 = d0 * d0 + d1 * d1 + d2 * d2 + d3 * d3;
#pragma unroll
            for (int o = 16; o; o >>= 1) s2 += __shfl_xor_sync(0xffffffffu, s2, o);
            float rstd = rsqrtf(s2 * (1.f / 128.f) + 1e-5f);
            xs[q][lane]      = d0 * rstd * lng[lane]      + lnb[lane];
            xs[q][lane + 32] = d1 * rstd * lng[lane + 32] + lnb[lane + 32];
            xs[q][lane + 64] = d2 * rstd * lng[lane + 64] + lnb[lane + 64];
            xs[q][lane + 96] = d3 * rstd * lng[lane + 96] + lnb[lane + 96];
        }
    }
    __syncthreads();

    // ---- layer2 + residual: h = xs @ nw2^T + nb2 + h ----
    {
        float acc[4][4];
#pragma unroll
        for (int j = 0; j < 4; j++)
#pragma unroll
            for (int cb = 0; cb < 4; cb++) acc[j][cb] = 0.f;

#pragma unroll 1
        for (int kk = 0; kk < LLv; kk += 4) {
            float4 w0 = *(const float4*)&nw2[(cl     ) * LLv + kk];
            float4 w1 = *(const float4*)&nw2[(cl + 32) * LLv + kk];
            float4 w2 = *(const float4*)&nw2[(cl + 64) * LLv + kk];
            float4 w3 = *(const float4*)&nw2[(cl + 96) * LLv + kk];
#pragma unroll
            for (int j = 0; j < 4; j++) {
                float4 x = *(const float4*)&xs[rg * 4 + j][kk];
                acc[j][0] = dot4(x, w0, acc[j][0]);
                acc[j][1] = dot4(x, w1, acc[j][1]);
                acc[j][2] = dot4(x, w2, acc[j][2]);
                acc[j][3] = dot4(x, w3, acc[j][3]);
            }
        }
#pragma unroll
        for (int cb = 0; cb < 4; cb++) {
            int c = cl + 32 * cb;
            float bi = nb2[c];
#pragma unroll
            for (int j = 0; j < 4; j++) {
                int r = rg * 4 + j;
                g_h[rowbase + r * LLv + c] = inp[r][c] + acc[j][cb] + bi;
            }
        }
    }
}

// ---------------- final mean over nodes --------------------------------------
__global__ void mean_kernel(float* __restrict__ out) {
    int b = blockIdx.x, t = threadIdx.x;   // 512 threads
    int l = t & 127, seg = t >> 7;
    const float* p = g_h + (b * NQv + seg * 256) * LLv + l;
    float s = 0.f;
#pragma unroll 8
    for (int q = 0; q < 256; q++) s += p[q * LLv];
    __shared__ float red[4][LLv];
    red[seg][l] = s;
    __syncthreads();
    if (seg == 0)
        out[b * LLv + l] =
            (red[0][l] + red[1][l] + red[2][l] + red[3][l]) * (1.f / 1024.f);
}

// ---------------- launch ------------------------------------------------------
extern "C" void kernel_launch(void* const* d_in, const int* in_sizes, int n_in,
                              void* d_out, int out_size) {
    const float* z0    = (const float*)d_in[0];
    const void*  eidx  = d_in[1];                 // int32 or int64, detected
    const float* eattr = (const float*)d_in[2];
    // d_in[3] = n_qubits (compile-time constant here)
    const float* ew1 = (const float*)d_in[4];
    const float* eb1 = (const float*)d_in[5];
    const float* ew2 = (const float*)d_in[6];
    const float* eb2 = (const float*)d_in[7];
    const float* nw1 = (const float*)d_in[8];
    const float* nb1 = (const float*)d_in[9];
    const float* lng = (const float*)d_in[10];
    const float* lnb = (const float*)d_in[11];
    const float* nw2 = (const float*)d_in[12];
    const float* nb2 = (const float*)d_in[13];
    float* out = (float*)d_out;

    detect_idx_kernel<<<1, 1>>>(eidx);
    pack_w1_kernel<<<(2 * LLv * 257 + 255) / 256, 256>>>(ew1);
    init_h_kernel<<<BB * NQv * LLv / 256, 256>>>(z0);

    for (int k = 0; k < 2; k++) {
        zero_magg_kernel<<<BB * NQv * LLv / 4 / 256, 256>>>();
        if (k == 0)
            base_kernel<<<BB, 128>>>(z0, eb1);
        else
            proj_kernel<<<BB * NQv / 64, 256>>>(eb1 + 128);

        edge_kernel<<<dim3(EEv / 64, BB), 256>>>(
            ew2 + k * LLv * LLv, eb2 + k * LLv, eidx, eattr, k);

        node_kernel<<<dim3(NQv / 32, BB), 256>>>(
            nw1 + k * LLv * 256, nb1 + k * LLv,
            lng + k * LLv, lnb + k * LLv,
            nw2 + k * LLv * LLv, nb2 + k * LLv);
    }

    mean_kernel<<<BB, 512>>>(out);
}

// round 2
// speedup vs baseline: 1.5101x; 1.5101x over previous
#include <cuda_runtime.h>

#define BB 64
#define NQv 1024
#define LLv 128
#define EEv 8192

// ---------------- scratch (static device globals; no allocations) ----------
__device__ float g_h[BB * NQv * LLv];      // node states
__device__ float g_A[BB * NQv * LLv];      // h @ W1a^T + b1   (round 1)
__device__ float g_Bv[BB * NQv * LLv];     // h @ W1b^T        (round 1)
__device__ float g_base[BB * LLv];         // round-0 collapsed layer-1
__device__ float g_w1a[2][LLv][LLv];       // packed e_w1[:, :, 0:128]
__device__ float g_w1b[2][LLv][LLv];       // packed e_w1[:, :, 128:256]
__device__ float g_w1c[2][LLv];            // packed e_w1[:, :, 256]
__device__ int   g_src[EEv];
__device__ int   g_tgt[EEv];
__device__ int   g_deg[NQv];
__device__ int   g_rowptr[NQv + 1];
__device__ int   g_csr_tgt[EEv];
__device__ float g_csr_ea[EEv];
__device__ int   g_is64;                   // edge_index dtype flag

__device__ __forceinline__ float dot4(float4 x, float4 w, float acc) {
    acc = fmaf(x.x, w.x, acc);
    acc = fmaf(x.y, w.y, acc);
    acc = fmaf(x.z, w.z, acc);
    acc = fmaf(x.w, w.w, acc);
    return acc;
}

// ---------------- setup kernels ---------------------------------------------
__global__ void detect_idx_kernel(const void* __restrict__ ei) {
    const long long* p = (const long long*)ei;
    int ok = 1;
    for (int i = 0; i < 64; i++) {
        long long v = p[i];
        if (v < 0 || v >= NQv) { ok = 0; break; }
    }
    g_is64 = ok;
}

__global__ void cvt_idx_kernel(const void* __restrict__ ei) {
    int i = blockIdx.x * 256 + threadIdx.x;   // over 2E
    if (i >= 2 * EEv) return;
    int v;
    if (g_is64) v = (int)((const long long*)ei)[i];
    else        v = ((const int*)ei)[i];
    if (i < EEv) g_src[i] = v;
    else         g_tgt[i - EEv] = v;
}

__global__ void pack_w1_kernel(const float* __restrict__ ew1) {
    int idx = blockIdx.x * blockDim.x + threadIdx.x;   // over 2*128*257
    if (idx >= 2 * LLv * 257) return;
    int k   = idx / (LLv * 257);
    int rem = idx % (LLv * 257);
    int c = rem / 257, j = rem % 257;
    float v = ew1[idx];
    if (j < 128)      g_w1a[k][c][j]       = v;
    else if (j < 256) g_w1b[k][c][j - 128] = v;
    else              g_w1c[k][c]          = v;
}

// deterministic CSR build: each thread owns one node and scans all edges
__global__ void deg_kernel() {
    __shared__ int ss[EEv];   // 32 KB
    int t = threadIdx.x;
    for (int i = t; i < EEv; i += 256) ss[i] = g_src[i];
    __syncthreads();
    int n = blockIdx.x * 256 + t;
    int c = 0;
#pragma unroll 8
    for (int e = 0; e < EEv; e++) c += (ss[e] == n);
    g_deg[n] = c;
}

__global__ void scan_kernel() {
    __shared__ int s[NQv];
    int t = threadIdx.x;
    s[t] = g_deg[t];
    __syncthreads();
    for (int off = 1; off < NQv; off <<= 1) {
        int v = (t >= off) ? s[t - off] : 0;
        __syncthreads();
        s[t] += v;
        __syncthreads();
    }
    g_rowptr[t + 1] = s[t];
    if (t == 0) g_rowptr[0] = 0;
}

__global__ void fill_kernel(const float* __restrict__ eattr) {
    __shared__ int ss[EEv];
    int t = threadIdx.x;
    for (int i = t; i < EEv; i += 256) ss[i] = g_src[i];
    __syncthreads();
    int n = blockIdx.x * 256 + t;
    int pos = g_rowptr[n];
    for (int e = 0; e < EEv; e++) {
        if (ss[e] == n) {
            g_csr_tgt[pos] = g_tgt[e];
            g_csr_ea[pos]  = eattr[e];
            pos++;
        }
    }
}

// round-0 collapsed layer-1 base: base[b][l] = z0[b] . (W1a[l]+W1b[l]) + b1[l]
__global__ void base_kernel(const float* __restrict__ z0,
                            const float* __restrict__ eb1) {
    int b = blockIdx.x, l = threadIdx.x;
    __shared__ float zs[LLv];
    zs[l] = z0[b * LLv + l];
    __syncthreads();
    float acc = eb1[l];
#pragma unroll 4
    for (int j = 0; j < LLv; j++)
        acc = fmaf(zs[j], g_w1a[0][l][j] + g_w1b[0][l][j], acc);
    g_base[b * LLv + l] = acc;
}

// ---------------- round-1 per-node projections ------------------------------
__global__ __launch_bounds__(256) void proj_kernel(const float* __restrict__ eb1) {
    __shared__ __align__(16) float inp[64][LLv];   // 32 KB
    int r0 = blockIdx.x * 64, t = threadIdx.x;

    const float4* hp = (const float4*)(g_h + r0 * LLv);
    float4* ip = (float4*)&inp[0][0];
#pragma unroll
    for (int i = 0; i < 8; i++) ip[t + i * 256] = hp[t + i * 256];
    __syncthreads();

    int cl = t & 31, rg = t >> 5;

#pragma unroll 1
    for (int target = 0; target < 2; target++) {
        const float* W = (target == 0) ? &g_w1a[1][0][0] : &g_w1b[1][0][0];
        float acc[8][4];
#pragma unroll
        for (int j = 0; j < 8; j++)
#pragma unroll
            for (int cb = 0; cb < 4; cb++) acc[j][cb] = 0.f;

#pragma unroll 1
        for (int kk = 0; kk < LLv; kk += 4) {
            float4 w0 = *(const float4*)&W[(cl     ) * LLv + kk];
            float4 w1 = *(const float4*)&W[(cl + 32) * LLv + kk];
            float4 w2 = *(const float4*)&W[(cl + 64) * LLv + kk];
            float4 w3 = *(const float4*)&W[(cl + 96) * LLv + kk];
#pragma unroll
            for (int j = 0; j < 8; j++) {
                float4 x = *(const float4*)&inp[rg * 8 + j][kk];
                acc[j][0] = dot4(x, w0, acc[j][0]);
                acc[j][1] = dot4(x, w1, acc[j][1]);
                acc[j][2] = dot4(x, w2, acc[j][2]);
                acc[j][3] = dot4(x, w3, acc[j][3]);
            }
        }
        float* out = (target == 0) ? g_A : g_Bv;
#pragma unroll
        for (int cb = 0; cb < 4; cb++) {
            int c = cl + 32 * cb;
            float bias = (target == 0) ? eb1[c] : 0.f;
#pragma unroll
            for (int j = 0; j < 8; j++)
                out[(r0 + rg * 8 + j) * LLv + c] = acc[j][cb] + bias;
        }
    }
}

// ---------------- fully fused per-round node kernel --------------------------
// aggregate relu edge-hidden (CSR gather) -> m_agg GEMM -> layer1 -> LN ->
// layer2 + residual. 32 nodes per block, 256 threads.
__global__ __launch_bounds__(256) void round_kernel(
    const float* __restrict__ z0,
    const float* __restrict__ ew2, const float* __restrict__ eb2,
    const float* __restrict__ nw1, const float* __restrict__ nb1,
    const float* __restrict__ lng, const float* __restrict__ lnb,
    const float* __restrict__ nw2, const float* __restrict__ nb2,
    int k)
{
    __shared__ __align__(16) float inp[32][256];   // [h | m_agg], 32 KB
    __shared__ __align__(16) float xs[32][LLv];    // hid_agg, then layer1 out
    // rowptr slice stored in inp[0][0..32] (as ints) until h-load overwrites it
    int* rp_s = (int*)&inp[0][0];

    int b = blockIdx.y, q0 = blockIdx.x * 32, t = threadIdx.x;
    int rowbase = (b * NQv + q0) * LLv;

    if (t < 33) rp_s[t] = g_rowptr[q0 + t];
    __syncthreads();

    int lane = t & 31, w = t >> 5;

    // ---- stage 1: hid_agg[n] = sum_{e: src=n} relu(A[n]+B[tgt]+ea*w1c) ----
    {
        float4 w1c4 = ((const float4*)&g_w1c[k][0])[lane];
#pragma unroll
        for (int j = 0; j < 4; j++) {
            int r = w * 4 + j;
            float4 a4;
            if (k == 0) a4 = ((const float4*)(g_base + b * LLv))[lane];
            else        a4 = ((const float4*)(g_A + rowbase + r * LLv))[lane];
            float4 acc = make_float4(0.f, 0.f, 0.f, 0.f);
            int e0 = rp_s[r], e1 = rp_s[r + 1];
            if (k == 0) {
                for (int e = e0; e < e1; e++) {
                    float ea = g_csr_ea[e];
                    acc.x += fmaxf(fmaf(ea, w1c4.x, a4.x), 0.f);
                    acc.y += fmaxf(fmaf(ea, w1c4.y, a4.y), 0.f);
                    acc.z += fmaxf(fmaf(ea, w1c4.z, a4.z), 0.f);
                    acc.w += fmaxf(fmaf(ea, w1c4.w, a4.w), 0.f);
                }
            } else {
                for (int e = e0; e < e1; e++) {
                    float ea = g_csr_ea[e];
                    int tg = g_csr_tgt[e];
                    float4 bv = ((const float4*)(g_Bv + (b * NQv + tg) * LLv))[lane];
                    acc.x += fmaxf(fmaf(ea, w1c4.x, a4.x + bv.x), 0.f);
                    acc.y += fmaxf(fmaf(ea, w1c4.y, a4.y + bv.y), 0.f);
                    acc.z += fmaxf(fmaf(ea, w1c4.z, a4.z + bv.z), 0.f);
                    acc.w += fmaxf(fmaf(ea, w1c4.w, a4.w + bv.w), 0.f);
                }
            }
            ((float4*)&xs[r][0])[lane] = acc;
        }
    }
    __syncthreads();

    int cl = lane, rg = w;

    // ---- stage 2: m_agg = hid_agg @ W2^T + deg*b2  -> inp[:, 128:256] ----
    {
        // capture degs before rp_s region is overwritten by h-load
        float dg[4];
#pragma unroll
        for (int j = 0; j < 4; j++) {
            int r = rg * 4 + j;
            dg[j] = (float)(rp_s[r + 1] - rp_s[r]);
        }

        float acc[4][4];
#pragma unroll
        for (int j = 0; j < 4; j++)
#pragma unroll
            for (int cb = 0; cb < 4; cb++) acc[j][cb] = 0.f;

#pragma unroll 1
        for (int kk = 0; kk < LLv; kk += 4) {
            float4 w0 = *(const float4*)&ew2[(cl     ) * LLv + kk];
            float4 w1 = *(const float4*)&ew2[(cl + 32) * LLv + kk];
            float4 w2 = *(const float4*)&ew2[(cl + 64) * LLv + kk];
            float4 w3 = *(const float4*)&ew2[(cl + 96) * LLv + kk];
#pragma unroll
            for (int j = 0; j < 4; j++) {
                float4 x = *(const float4*)&xs[rg * 4 + j][kk];
                acc[j][0] = dot4(x, w0, acc[j][0]);
                acc[j][1] = dot4(x, w1, acc[j][1]);
                acc[j][2] = dot4(x, w2, acc[j][2]);
                acc[j][3] = dot4(x, w3, acc[j][3]);
            }
        }
        __syncthreads();   // everyone done reading rp_s / writing stage-2 math
#pragma unroll
        for (int cb = 0; cb < 4; cb++) {
            int c = cl + 32 * cb;
            float bi = eb2[c];
#pragma unroll
            for (int j = 0; j < 4; j++)
                inp[rg * 4 + j][128 + c] = acc[j][cb] + dg[j] * bi;
        }
    }

    // ---- stage 2b: load h rows into inp[:, 0:128] ----
    {
#pragma unroll
        for (int i = 0; i < 4; i++) {
            int idx = t + i * 256;
            int r = idx >> 5, j4 = idx & 31;
            float4 hv = (k == 0) ? ((const float4*)(z0 + b * LLv))[j4]
                                 : ((const float4*)(g_h + rowbase + r * LLv))[j4];
            ((float4*)&inp[r][0])[j4] = hv;
        }
    }
    __syncthreads();

    // ---- stage 3: x = relu([h|m_agg] @ nw1^T + nb1) -> xs ----
    {
        float acc[4][4];
#pragma unroll
        for (int j = 0; j < 4; j++)
#pragma unroll
            for (int cb = 0; cb < 4; cb++) acc[j][cb] = 0.f;

#pragma unroll 1
        for (int kk = 0; kk < 256; kk += 4) {
            float4 w0 = *(const float4*)&nw1[(cl     ) * 256 + kk];
            float4 w1 = *(const float4*)&nw1[(cl + 32) * 256 + kk];
            float4 w2 = *(const float4*)&nw1[(cl + 64) * 256 + kk];
            float4 w3 = *(const float4*)&nw1[(cl + 96) * 256 + kk];
#pragma unroll
            for (int j = 0; j < 4; j++) {
                float4 x = *(const float4*)&inp[rg * 4 + j][kk];
                acc[j][0] = dot4(x, w0, acc[j][0]);
                acc[j][1] = dot4(x, w1, acc[j][1]);
                acc[j][2] = dot4(x, w2, acc[j][2]);
                acc[j][3] = dot4(x, w3, acc[j][3]);
            }
        }
        __syncthreads();   // xs (hid_agg) no longer needed; safe to overwrite
#pragma unroll
        for (int cb = 0; cb < 4; cb++) {
            int c = cl + 32 * cb;
            float bi = nb1[c];
#pragma unroll
            for (int j = 0; j < 4; j++)
                xs[rg * 4 + j][c] = fmaxf(acc[j][cb] + bi, 0.f);
        }
    }
    __syncthreads();

    // ---- stage 4: LayerNorm over L=128 (warp handles 4 rows) ----
    {
#pragma unroll
        for (int j = 0; j < 4; j++) {
            int q = w * 4 + j;
            float v0 = xs[q][lane], v1 = xs[q][lane + 32];
            float v2 = xs[q][lane + 64], v3 = xs[q][lane + 96];
            float s = v0 + v1 + v2 + v3;
#pragma unroll
            for (int o = 16; o; o >>= 1) s += __shfl_xor_sync(0xffffffffu, s, o);
            float mu = s * (1.f / 128.f);
            float d0 = v0 - mu, d1 = v1 - mu, d2 = v2 - mu, d3 = v3 - mu;
            float s2 = d0 * d0 + d1 * d1 + d2 * d2 + d3 * d3;
#pragma unroll
            for (int o = 16; o; o >>= 1) s2 += __shfl_xor_sync(0xffffffffu, s2, o);
            float rstd = rsqrtf(s2 * (1.f / 128.f) + 1e-5f);
            xs[q][lane]      = d0 * rstd * lng[lane]      + lnb[lane];
            xs[q][lane + 32] = d1 * rstd * lng[lane + 32] + lnb[lane + 32];
            xs[q][lane + 64] = d2 * rstd * lng[lane + 64] + lnb[lane + 64];
            xs[q][lane + 96] = d3 * rstd * lng[lane + 96] + lnb[lane + 96];
        }
    }
    __syncthreads();

    // ---- stage 5: h = xs @ nw2^T + nb2 + h ----
    {
        float acc[4][4];
#pragma unroll
        for (int j = 0; j < 4; j++)
#pragma unroll
            for (int cb = 0; cb < 4; cb++) acc[j][cb] = 0.f;

#pragma unroll 1
        for (int kk = 0; kk < LLv; kk += 4) {
            float4 w0 = *(const float4*)&nw2[(cl     ) * LLv + kk];
            float4 w1 = *(const float4*)&nw2[(cl + 32) * LLv + kk];
            float4 w2 = *(const float4*)&nw2[(cl + 64) * LLv + kk];
            float4 w3 = *(const float4*)&nw2[(cl + 96) * LLv + kk];
#pragma unroll
            for (int j = 0; j < 4; j++) {
                float4 x = *(const float4*)&xs[rg * 4 + j][kk];
                acc[j][0] = dot4(x, w0, acc[j][0]);
                acc[j][1] = dot4(x, w1, acc[j][1]);
                acc[j][2] = dot4(x, w2, acc[j][2]);
                acc[j][3] = dot4(x, w3, acc[j][3]);
            }
        }
#pragma unroll
        for (int cb = 0; cb < 4; cb++) {
            int c = cl + 32 * cb;
            float bi = nb2[c];
#pragma unroll
            for (int j = 0; j < 4; j++) {
                int r = rg * 4 + j;
                g_h[rowbase + r * LLv + c] = inp[r][c] + acc[j][cb] + bi;
            }
        }
    }
}

// ---------------- final mean over nodes --------------------------------------
__global__ void mean_kernel(float* __restrict__ out) {
    int b = blockIdx.x, t = threadIdx.x;   // 512 threads
    int l = t & 127, seg = t >> 7;
    const float* p = g_h + (b * NQv + seg * 256) * LLv + l;
    float s = 0.f;
#pragma unroll 8
    for (int q = 0; q < 256; q++) s += p[q * LLv];
    __shared__ float red[4][LLv];
    red[seg][l] = s;
    __syncthreads();
    if (seg == 0)
        out[b * LLv + l] =
            (red[0][l] + red[1][l] + red[2][l] + red[3][l]) * (1.f / 1024.f);
}

// ---------------- launch ------------------------------------------------------
extern "C" void kernel_launch(void* const* d_in, const int* in_sizes, int n_in,
                              void* d_out, int out_size) {
    const float* z0    = (const float*)d_in[0];
    const void*  eidx  = d_in[1];
    const float* eattr = (const float*)d_in[2];
    const float* ew1 = (const float*)d_in[4];
    const float* eb1 = (const float*)d_in[5];
    const float* ew2 = (const float*)d_in[6];
    const float* eb2 = (const float*)d_in[7];
    const float* nw1 = (const float*)d_in[8];
    const float* nb1 = (const float*)d_in[9];
    const float* lng = (const float*)d_in[10];
    const float* lnb = (const float*)d_in[11];
    const float* nw2 = (const float*)d_in[12];
    const float* nb2 = (const float*)d_in[13];
    float* out = (float*)d_out;

    detect_idx_kernel<<<1, 1>>>(eidx);
    cvt_idx_kernel<<<(2 * EEv + 255) / 256, 256>>>(eidx);
    pack_w1_kernel<<<(2 * LLv * 257 + 255) / 256, 256>>>(ew1);
    deg_kernel<<<NQv / 256, 256>>>();
    scan_kernel<<<1, NQv>>>();
    fill_kernel<<<NQv / 256, 256>>>(eattr);

    base_kernel<<<BB, 128>>>(z0, eb1);
    round_kernel<<<dim3(NQv / 32, BB), 256>>>(
        z0, ew2, eb2, nw1, nb1, lng, lnb, nw2, nb2, 0);

    proj_kernel<<<BB * NQv / 64, 256>>>(eb1 + 128);
    round_kernel<<<dim3(NQv / 32, BB), 256>>>(
        z0,
        ew2 + LLv * LLv, eb2 + LLv,
        nw1 + LLv * 256, nb1 + LLv,
        lng + LLv, lnb + LLv,
        nw2 + LLv * LLv, nb2 + LLv, 1);

    mean_kernel<<<BB, 512>>>(out);
}

// round 3
// speedup vs baseline: 5.1828x; 3.4321x over previous
#include <cuda_runtime.h>

#define BB 64
#define NQv 1024
#define LLv 128
#define EEv 8192

// ---------------- scratch (static device globals; no allocations) ----------
__device__ float g_h[BB * NQv * LLv];      // node states
__device__ float g_A[BB * NQv * LLv];      // h @ W1a^T + b1   (round 1)
__device__ float g_Bv[BB * NQv * LLv];     // h @ W1b^T        (round 1)
__device__ float g_base[BB * LLv];         // round-0 collapsed layer-1
__device__ float g_w1a[2][LLv][LLv];       // packed e_w1[:, :, 0:128]
__device__ float g_w1b[2][LLv][LLv];       // packed e_w1[:, :, 128:256]
__device__ float g_w1ab[LLv * LLv];        // w1a[0]+w1b[0] (round-0 collapse)
__device__ float g_w1c[2][LLv];            // packed e_w1[:, :, 256]
__device__ int   g_src[EEv];
__device__ int   g_tgt[EEv];
__device__ int   g_deg[NQv];
__device__ int   g_rowptr[NQv + 1];
__device__ int   g_csr_tgt[EEv];
__device__ float g_csr_ea[EEv];
__device__ int   g_is64;                   // edge_index dtype flag

#define WS_FLOATS 2064                     // 16 x 129 weight tile (k-major)

// ---------------- staged register-tile GEMM ---------------------------------
// C[ROWS*8 rows][128 cols] = Xs[rows][K] @ Wg[128][K]^T,  256 threads.
// Weight chunk (16 k x 128 cols) staged into smem k-major with stride 129:
// compute reads Ws[k*129 + cl + 32*cb] -> consecutive lanes, conflict-free;
// activation reads are warp-broadcast LDS.128. Trailing barrier lets callers
// overlay Ws on smem regions their epilogues then reuse.
template<int ROWS, int K>
__device__ __forceinline__ void gemm_staged(
    float (&acc)[ROWS][4], const float* Xs, int xstride,
    const float* __restrict__ Wg, float* Ws, int t)
{
    int cl = t & 31, rg = t >> 5;
#pragma unroll
    for (int j = 0; j < ROWS; j++)
#pragma unroll
        for (int cb = 0; cb < 4; cb++) acc[j][cb] = 0.f;

#pragma unroll 1
    for (int kk = 0; kk < K; kk += 16) {
        __syncthreads();                       // prior users of Ws done
#pragma unroll
        for (int rep = 0; rep < 2; rep++) {
            int idx = rep * 256 + t;           // 0..511
            int c = idx >> 2;                  // output column 0..127
            int p = (idx & 3) * 4;             // k offset within chunk
            float4 v = *(const float4*)&Wg[c * K + kk + p];
            Ws[(p + 0) * 129 + c] = v.x;
            Ws[(p + 1) * 129 + c] = v.y;
            Ws[(p + 2) * 129 + c] = v.z;
            Ws[(p + 3) * 129 + c] = v.w;
        }
        __syncthreads();
#pragma unroll
        for (int kq = 0; kq < 16; kq += 4) {
            float xv[ROWS][4];
#pragma unroll
            for (int j = 0; j < ROWS; j++) {
                float4 x4 = *(const float4*)&Xs[(rg * ROWS + j) * xstride + kk + kq];
                xv[j][0] = x4.x; xv[j][1] = x4.y; xv[j][2] = x4.z; xv[j][3] = x4.w;
            }
#pragma unroll
            for (int i = 0; i < 4; i++) {
                int k = kq + i;
                float w0 = Ws[k * 129 + cl];
                float w1 = Ws[k * 129 + cl + 32];
                float w2 = Ws[k * 129 + cl + 64];
                float w3 = Ws[k * 129 + cl + 96];
#pragma unroll
                for (int j = 0; j < ROWS; j++) {
                    acc[j][0] = fmaf(xv[j][i], w0, acc[j][0]);
                    acc[j][1] = fmaf(xv[j][i], w1, acc[j][1]);
                    acc[j][2] = fmaf(xv[j][i], w2, acc[j][2]);
                    acc[j][3] = fmaf(xv[j][i], w3, acc[j][3]);
                }
            }
        }
    }
    __syncthreads();                           // all Ws reads complete
}

// ---------------- setup kernels ---------------------------------------------
__global__ void detect_idx_kernel(const void* __restrict__ ei) {
    const long long* p = (const long long*)ei;
    int ok = 1;
    for (int i = 0; i < 64; i++) {
        long long v = p[i];
        if (v < 0 || v >= NQv) { ok = 0; break; }
    }
    g_is64 = ok;
}

__global__ void cvt_idx_kernel(const void* __restrict__ ei) {
    int i = blockIdx.x * 256 + threadIdx.x;   // over 2E
    if (i >= 2 * EEv) return;
    int v;
    if (g_is64) v = (int)((const long long*)ei)[i];
    else        v = ((const int*)ei)[i];
    if (i < EEv) g_src[i] = v;
    else         g_tgt[i - EEv] = v;
}

__global__ void pack_w1_kernel(const float* __restrict__ ew1) {
    int idx = blockIdx.x * blockDim.x + threadIdx.x;   // over 2*128*257
    if (idx >= 2 * LLv * 257) return;
    int k   = idx / (LLv * 257);
    int rem = idx % (LLv * 257);
    int c = rem / 257, j = rem % 257;
    float v = ew1[idx];
    if (j < 128)      g_w1a[k][c][j]       = v;
    else if (j < 256) g_w1b[k][c][j - 128] = v;
    else              g_w1c[k][c]          = v;
}

__global__ void sum_w_kernel() {
    int idx = blockIdx.x * 256 + threadIdx.x;   // over 128*128
    g_w1ab[idx] = (&g_w1a[0][0][0])[idx] + (&g_w1b[0][0][0])[idx];
}

// warp-per-node CSR build (deterministic edge order preserved)
__global__ void deg_kernel() {              // NQv/8 blocks x 256
    __shared__ int ss[EEv];
    int t = threadIdx.x;
    for (int i = t; i < EEv; i += 256) ss[i] = g_src[i];
    __syncthreads();
    int lane = t & 31;
    int n = blockIdx.x * 8 + (t >> 5);
    int cnt = 0;
    for (int base = 0; base < EEv; base += 32) {
        int v = ss[base + lane];
        cnt += __popc(__ballot_sync(0xffffffffu, v == n));
    }
    if (lane == 0) g_deg[n] = cnt;
}

__global__ void scan_kernel() {
    __shared__ int s[NQv];
    int t = threadIdx.x;
    s[t] = g_deg[t];
    __syncthreads();
    for (int off = 1; off < NQv; off <<= 1) {
        int v = (t >= off) ? s[t - off] : 0;
        __syncthreads();
        s[t] += v;
        __syncthreads();
    }
    g_rowptr[t + 1] = s[t];
    if (t == 0) g_rowptr[0] = 0;
}

__global__ void fill_kernel(const float* __restrict__ eattr) {   // NQv/8 x 256
    __shared__ int ss[EEv];
    int t = threadIdx.x;
    for (int i = t; i < EEv; i += 256) ss[i] = g_src[i];
    __syncthreads();
    int lane = t & 31;
    int n = blockIdx.x * 8 + (t >> 5);
    int pos = g_rowptr[n];
    for (int base = 0; base < EEv; base += 32) {
        int v = ss[base + lane];
        unsigned m = __ballot_sync(0xffffffffu, v == n);
        if (v == n) {
            int ofs = __popc(m & ((1u << lane) - 1u));
            g_csr_tgt[pos + ofs] = g_tgt[base + lane];
            g_csr_ea[pos + ofs]  = eattr[base + lane];
        }
        pos += __popc(m);
    }
}

// round-0 collapsed layer-1: base[b][l] = z0[b] . (W1a[0]+W1b[0])[l] + b1[l]
__global__ __launch_bounds__(256) void base_kernel(
    const float* __restrict__ z0, const float* __restrict__ eb1)
{
    __shared__ __align__(16) float zs[64][LLv];   // 32 KB
    __shared__ float Ws[WS_FLOATS];
    int t = threadIdx.x;
    const float4* zp = (const float4*)z0;
    float4* sp = (float4*)&zs[0][0];
#pragma unroll
    for (int i = 0; i < 8; i++) sp[t + i * 256] = zp[t + i * 256];
    __syncthreads();

    float acc[8][4];
    gemm_staged<8, 128>(acc, &zs[0][0], 128, g_w1ab, Ws, t);

    int cl = t & 31, rg = t >> 5;
#pragma unroll
    for (int cb = 0; cb < 4; cb++) {
        int c = cl + 32 * cb;
        float bi = eb1[c];
#pragma unroll
        for (int j = 0; j < 8; j++)
            g_base[(rg * 8 + j) * LLv + c] = acc[j][cb] + bi;
    }
}

// ---------------- round-1 per-node projections ------------------------------
__global__ __launch_bounds__(256) void proj_kernel(const float* __restrict__ eb1) {
    __shared__ __align__(16) float inp[64][LLv];   // 32 KB
    __shared__ float Ws[WS_FLOATS];
    int r0 = blockIdx.x * 64, t = threadIdx.x;

    const float4* hp = (const float4*)(g_h + r0 * LLv);
    float4* ip = (float4*)&inp[0][0];
#pragma unroll
    for (int i = 0; i < 8; i++) ip[t + i * 256] = hp[t + i * 256];
    __syncthreads();

    int cl = t & 31, rg = t >> 5;
    float acc[8][4];

    gemm_staged<8, 128>(acc, &inp[0][0], 128, &g_w1a[1][0][0], Ws, t);
#pragma unroll
    for (int cb = 0; cb < 4; cb++) {
        int c = cl + 32 * cb;
        float bi = eb1[c];
#pragma unroll
        for (int j = 0; j < 8; j++)
            g_A[(r0 + rg * 8 + j) * LLv + c] = acc[j][cb] + bi;
    }

    gemm_staged<8, 128>(acc, &inp[0][0], 128, &g_w1b[1][0][0], Ws, t);
#pragma unroll
    for (int cb = 0; cb < 4; cb++) {
        int c = cl + 32 * cb;
#pragma unroll
        for (int j = 0; j < 8; j++)
            g_Bv[(r0 + rg * 8 + j) * LLv + c] = acc[j][cb];
    }
}

// ---------------- fully fused per-round node kernel --------------------------
__global__ __launch_bounds__(256) void round_kernel(
    const float* __restrict__ z0,
    const float* __restrict__ ew2, const float* __restrict__ eb2,
    const float* __restrict__ nw1, const float* __restrict__ nb1,
    const float* __restrict__ lng, const float* __restrict__ lnb,
    const float* __restrict__ nw2, const float* __restrict__ nb2,
    int k)
{
    __shared__ __align__(16) float inp[32][256];   // [h | m_agg], 32 KB
    __shared__ __align__(16) float xs[32][LLv];    // hid_agg, then layer1 out
    int* rp_s = (int*)&inp[0][0];                  // rowptr slice (row 0)

    int b = blockIdx.y, q0 = blockIdx.x * 32, t = threadIdx.x;
    int rowbase = (b * NQv + q0) * LLv;

    if (t < 33) rp_s[t] = g_rowptr[q0 + t];
    __syncthreads();

    int lane = t & 31, w = t >> 5;
    int cl = lane, rg = w;

    // ---- stage 1: hid_agg[n] = sum_{e: src=n} relu(A[n]+B[tgt]+ea*w1c) ----
    {
        float4 w1c4 = ((const float4*)&g_w1c[k][0])[lane];
#pragma unroll
        for (int j = 0; j < 4; j++) {
            int r = w * 4 + j;
            float4 a4;
            if (k == 0) a4 = ((const float4*)(g_base + b * LLv))[lane];
            else        a4 = ((const float4*)(g_A + rowbase + r * LLv))[lane];
            float4 acc = make_float4(0.f, 0.f, 0.f, 0.f);
            int e0 = rp_s[r], e1 = rp_s[r + 1];
            if (k == 0) {
                for (int e = e0; e < e1; e++) {
                    float ea = g_csr_ea[e];
                    acc.x += fmaxf(fmaf(ea, w1c4.x, a4.x), 0.f);
                    acc.y += fmaxf(fmaf(ea, w1c4.y, a4.y), 0.f);
                    acc.z += fmaxf(fmaf(ea, w1c4.z, a4.z), 0.f);
                    acc.w += fmaxf(fmaf(ea, w1c4.w, a4.w), 0.f);
                }
            } else {
                for (int e = e0; e < e1; e++) {
                    float ea = g_csr_ea[e];
                    int tg = g_csr_tgt[e];
                    float4 bv = ((const float4*)(g_Bv + (b * NQv + tg) * LLv))[lane];
                    acc.x += fmaxf(fmaf(ea, w1c4.x, a4.x + bv.x), 0.f);
                    acc.y += fmaxf(fmaf(ea, w1c4.y, a4.y + bv.y), 0.f);
                    acc.z += fmaxf(fmaf(ea, w1c4.z, a4.z + bv.z), 0.f);
                    acc.w += fmaxf(fmaf(ea, w1c4.w, a4.w + bv.w), 0.f);
                }
            }
            ((float4*)&xs[r][0])[lane] = acc;
        }
    }
    __syncthreads();

    // capture degrees before anything overwrites rp_s
    float dg[4];
#pragma unroll
    for (int j = 0; j < 4; j++) {
        int r = rg * 4 + j;
        dg[j] = (float)(rp_s[r + 1] - rp_s[r]);
    }

    // ---- stage 2: m_agg = hid_agg @ W2^T + deg*b2 -> inp[:, 128:256] ----
    // Ws overlays inp starting at row 1 (cols 0..127 region dead; guarded by
    // gemm's trailing barrier; epilogue writes only cols 128..255)
    {
        float acc[4][4];
        gemm_staged<4, 128>(acc, &xs[0][0], 128, ew2, &inp[1][0], t);
#pragma unroll
        for (int cb = 0; cb < 4; cb++) {
            int c = cl + 32 * cb;
            float bi = eb2[c];
#pragma unroll
            for (int j = 0; j < 4; j++)
                inp[rg * 4 + j][128 + c] = acc[j][cb] + dg[j] * bi;
        }
    }

    // ---- stage 2b: load h rows into inp[:, 0:128] ----
#pragma unroll
    for (int i = 0; i < 4; i++) {
        int idx = t + i * 256;
        int r = idx >> 5, j4 = idx & 31;
        float4 hv = (k == 0) ? ((const float4*)(z0 + b * LLv))[j4]
                             : ((const float4*)(g_h + rowbase + r * LLv))[j4];
        ((float4*)&inp[r][0])[j4] = hv;
    }
    __syncthreads();

    // ---- stage 3: x = relu([h|m_agg] @ nw1^T + nb1) -> xs ----
    // Ws overlays xs (dead until epilogue; guarded by trailing barrier)
    {
        float acc[4][4];
        gemm_staged<4, 256>(acc, &inp[0][0], 256, nw1, &xs[0][0], t);
#pragma unroll
        for (int cb = 0; cb < 4; cb++) {
            int c = cl + 32 * cb;
            float bi = nb1[c];
#pragma unroll
            for (int j = 0; j < 4; j++)
                xs[rg * 4 + j][c] = fmaxf(acc[j][cb] + bi, 0.f);
        }
    }
    __syncthreads();

    // ---- stage 4: LayerNorm over L=128 (warp handles 4 rows) ----
    {
#pragma unroll
        for (int j = 0; j < 4; j++) {
            int q = w * 4 + j;
            float v0 = xs[q][lane], v1 = xs[q][lane + 32];
            float v2 = xs[q][lane + 64], v3 = xs[q][lane + 96];
            float s = v0 + v1 + v2 + v3;
#pragma unroll
            for (int o = 16; o; o >>= 1) s += __shfl_xor_sync(0xffffffffu, s, o);
            float mu = s * (1.f / 128.f);
            float d0 = v0 - mu, d1 = v1 - mu, d2 = v2 - mu, d3 = v3 - mu;
            float s2 = d0 * d0 + d1 * d1 + d2 * d2 + d3 * d3;
#pragma unroll
            for (int o = 16; o; o >>= 1) s2 += __shfl_xor_sync(0xffffffffu, s2, o);
            float rstd = rsqrtf(s2 * (1.f / 128.f) + 1e-5f);
            xs[q][lane]      = d0 * rstd * lng[lane]      + lnb[lane];
            xs[q][lane + 32] = d1 * rstd * lng[lane + 32] + lnb[lane + 32];
            xs[q][lane + 64] = d2 * rstd * lng[lane + 64] + lnb[lane + 64];
            xs[q][lane + 96] = d3 * rstd * lng[lane + 96] + lnb[lane + 96];
        }
    }
    __syncthreads();

    // ---- stage 5: h = xs @ nw2^T + nb2 + h ----
    // Ws overlays all of inp (dead); residual re-read from global
    {
        float acc[4][4];
        gemm_staged<4, 128>(acc, &xs[0][0], 128, nw2, &inp[0][0], t);
#pragma unroll
        for (int cb = 0; cb < 4; cb++) {
            int c = cl + 32 * cb;
            float bi = nb2[c];
#pragma unroll
            for (int j = 0; j < 4; j++) {
                int r = rg * 4 + j;
                float res = (k == 0) ? z0[b * LLv + c]
                                     : g_h[rowbase + r * LLv + c];
                g_h[rowbase + r * LLv + c] = res + acc[j][cb] + bi;
            }
        }
    }
}

// ---------------- final mean over nodes --------------------------------------
__global__ void mean_kernel(float* __restrict__ out) {
    int b = blockIdx.x, t = threadIdx.x;   // 512 threads
    int l = t & 127, seg = t >> 7;
    const float* p = g_h + (b * NQv + seg * 256) * LLv + l;
    float s = 0.f;
#pragma unroll 8
    for (int q = 0; q < 256; q++) s += p[q * LLv];
    __shared__ float red[4][LLv];
    red[seg][l] = s;
    __syncthreads();
    if (seg == 0)
        out[b * LLv + l] =
            (red[0][l] + red[1][l] + red[2][l] + red[3][l]) * (1.f / 1024.f);
}

// ---------------- launch ------------------------------------------------------
extern "C" void kernel_launch(void* const* d_in, const int* in_sizes, int n_in,
                              void* d_out, int out_size) {
    const float* z0    = (const float*)d_in[0];
    const void*  eidx  = d_in[1];
    const float* eattr = (const float*)d_in[2];
    const float* ew1 = (const float*)d_in[4];
    const float* eb1 = (const float*)d_in[5];
    const float* ew2 = (const float*)d_in[6];
    const float* eb2 = (const float*)d_in[7];
    const float* nw1 = (const float*)d_in[8];
    const float* nb1 = (const float*)d_in[9];
    const float* lng = (const float*)d_in[10];
    const float* lnb = (const float*)d_in[11];
    const float* nw2 = (const float*)d_in[12];
    const float* nb2 = (const float*)d_in[13];
    float* out = (float*)d_out;

    detect_idx_kernel<<<1, 1>>>(eidx);
    cvt_idx_kernel<<<(2 * EEv + 255) / 256, 256>>>(eidx);
    pack_w1_kernel<<<(2 * LLv * 257 + 255) / 256, 256>>>(ew1);
    sum_w_kernel<<<LLv * LLv / 256, 256>>>();
    deg_kernel<<<NQv / 8, 256>>>();
    scan_kernel<<<1, NQv>>>();
    fill_kernel<<<NQv / 8, 256>>>(eattr);

    base_kernel<<<1, 256>>>(z0, eb1);
    round_kernel<<<dim3(NQv / 32, BB), 256>>>(
        z0, ew2, eb2, nw1, nb1, lng, lnb, nw2, nb2, 0);

    proj_kernel<<<BB * NQv / 64, 256>>>(eb1 + 128);
    round_kernel<<<dim3(NQv / 32, BB), 256>>>(
        z0,
        ew2 + LLv * LLv, eb2 + LLv,
        nw1 + LLv * 256, nb1 + LLv,
        lng + LLv, lnb + LLv,
        nw2 + LLv * LLv, nb2 + LLv, 1);

    mean_kernel<<<BB, 512>>>(out);
}

// round 4
// speedup vs baseline: 8.6330x; 1.6657x over previous
#include <cuda_runtime.h>

#define BB 64
#define NQv 1024
#define LLv 128
#define EEv 8192

// ---------------- scratch (static device globals; no allocations) ----------
__device__ float g_h[BB * NQv * LLv];      // node states (exact fp32)
__device__ float g_A[BB * NQv * LLv];      // h @ W1a^T + b1   (round 1)
__device__ float g_Bv[BB * NQv * LLv];     // h @ W1b^T        (round 1)
__device__ float g_base[BB * LLv];         // round-0 collapsed layer-1
__device__ float g_w1a[2][LLv][LLv];       // packed e_w1[:, :, 0:128]
__device__ float g_w1b[2][LLv][LLv];       // packed e_w1[:, :, 128:256]
__device__ float g_w1ab[LLv * LLv];        // w1a[0]+w1b[0] (round-0 collapse)
__device__ float g_w1c[2][LLv];            // packed e_w1[:, :, 256]
// tf32-rounded weight copies (for MMA)
__device__ float g_ew2r[2 * LLv * LLv];
__device__ float g_nw1r[2 * LLv * 256];
__device__ float g_nw2r[2 * LLv * LLv];
__device__ float g_w1ar[LLv * LLv];
__device__ float g_w1br[LLv * LLv];
__device__ int   g_src[EEv];
__device__ int   g_tgt[EEv];
__device__ int   g_deg[NQv];
__device__ int   g_rowptr[NQv + 1];
__device__ int   g_csr_tgt[EEv];
__device__ float g_csr_ea[EEv];
__device__ int   g_is64;

// ---------------- tf32 helpers ------------------------------------------------
__device__ __forceinline__ unsigned f2tf32(float x) {
    unsigned r;
    asm("cvt.rna.tf32.f32 %0, %1;" : "=r"(r) : "f"(x));
    return r;
}
__device__ __forceinline__ float f2tf32f(float x) {
    return __uint_as_float(f2tf32(x));
}
__device__ __forceinline__ void mma_tf32(float (&c)[4],
    unsigned a0, unsigned a1, unsigned a2, unsigned a3,
    unsigned b0, unsigned b1)
{
    asm volatile(
        "mma.sync.aligned.m16n8k8.row.col.f32.tf32.tf32.f32 "
        "{%0,%1,%2,%3}, {%4,%5,%6,%7}, {%8,%9}, {%0,%1,%2,%3};"
        : "+f"(c[0]), "+f"(c[1]), "+f"(c[2]), "+f"(c[3])
        : "r"(a0), "r"(a1), "r"(a2), "r"(a3), "r"(b0), "r"(b1));
}

#define WSS 68   // weight tile stride (floats). 68 = 4*17 -> conflict-free frags

// ---------------- warp-tiled tf32 GEMM, M=64 x N=128, 8 warps -----------------
// C = Xs[64][K] @ Wg[128][K]^T. Warp w: rows [wm*32,+32), cols [wn*32,+32),
// wm = w&1, wn = w>>1. acc layout per PTX m16n8k8 C fragments.
// Xs stride must be == 4 (mod 32) with odd multiplier of 4 (132, 260 OK).
// Wg is tf32-rounded fp32 in global, row-major [128][K]. Ws = 128*68 floats.
template<int K>
__device__ __forceinline__ void mma_gemm64(
    float (&c)[2][4][4], const float* Xs, int xstride,
    const float* __restrict__ Wg, float* Ws, int t)
{
    int lane = t & 31, w = t >> 5;
    int g = lane >> 2, tig = lane & 3;
    int wm = w & 1, wn = w >> 1;
#pragma unroll
    for (int mr = 0; mr < 2; mr++)
#pragma unroll
        for (int nf = 0; nf < 4; nf++)
#pragma unroll
            for (int i = 0; i < 4; i++) c[mr][nf][i] = 0.f;

#pragma unroll 1
    for (int kk = 0; kk < K; kk += 64) {
        __syncthreads();                     // prior Ws readers done
#pragma unroll
        for (int rep = 0; rep < 8; rep++) {
            int idx = rep * 256 + t;         // 0..2047 float4 units
            int cc = idx >> 4;               // out col 0..127
            int p  = (idx & 15) << 2;        // k offset 0..60
            float4 v = *(const float4*)&Wg[cc * K + kk + p];
            float* d = &Ws[cc * WSS + p];
            d[0] = v.x; d[1] = v.y; d[2] = v.z; d[3] = v.w;
        }
        __syncthreads();
#pragma unroll
        for (int ks = 0; ks < 8; ks++) {
            int k0 = ks * 8;
            unsigned a[2][4], b[4][2];
#pragma unroll
            for (int mr = 0; mr < 2; mr++) {
                const float* xr = Xs + (wm * 32 + mr * 16 + g) * xstride + kk + k0;
                const float* xr8 = xr + 8 * xstride;
                a[mr][0] = __float_as_uint(xr[tig]);
                a[mr][1] = __float_as_uint(xr8[tig]);
                a[mr][2] = __float_as_uint(xr[tig + 4]);
                a[mr][3] = __float_as_uint(xr8[tig + 4]);
            }
#pragma unroll
            for (int nf = 0; nf < 4; nf++) {
                const float* wr = Ws + (wn * 32 + nf * 8 + g) * WSS + k0;
                b[nf][0] = __float_as_uint(wr[tig]);
                b[nf][1] = __float_as_uint(wr[tig + 4]);
            }
#pragma unroll
            for (int mr = 0; mr < 2; mr++)
#pragma unroll
                for (int nf = 0; nf < 4; nf++)
                    mma_tf32(c[mr][nf], a[mr][0], a[mr][1], a[mr][2], a[mr][3],
                             b[nf][0], b[nf][1]);
        }
    }
}
// acc element (mr, nf, i) -> row = wm*32 + mr*16 + g + (i>>1)*8
//                            col = wn*32 + nf*8 + 2*tig + (i&1)

// ---------------- setup kernels ---------------------------------------------
__global__ void detect_idx_kernel(const void* __restrict__ ei) {
    const long long* p = (const long long*)ei;
    int ok = 1;
    for (int i = 0; i < 64; i++) {
        long long v = p[i];
        if (v < 0 || v >= NQv) { ok = 0; break; }
    }
    g_is64 = ok;
}

__global__ void cvt_idx_kernel(const void* __restrict__ ei) {
    int i = blockIdx.x * 256 + threadIdx.x;
    if (i >= 2 * EEv) return;
    int v;
    if (g_is64) v = (int)((const long long*)ei)[i];
    else        v = ((const int*)ei)[i];
    if (i < EEv) g_src[i] = v;
    else         g_tgt[i - EEv] = v;
}

__global__ void pack_w1_kernel(const float* __restrict__ ew1) {
    int idx = blockIdx.x * blockDim.x + threadIdx.x;
    if (idx >= 2 * LLv * 257) return;
    int k   = idx / (LLv * 257);
    int rem = idx % (LLv * 257);
    int c = rem / 257, j = rem % 257;
    float v = ew1[idx];
    if (j < 128)      g_w1a[k][c][j]       = v;
    else if (j < 256) g_w1b[k][c][j - 128] = v;
    else              g_w1c[k][c]          = v;
}

__global__ void sum_w_kernel() {
    int idx = blockIdx.x * 256 + threadIdx.x;
    g_w1ab[idx] = (&g_w1a[0][0][0])[idx] + (&g_w1b[0][0][0])[idx];
}

// tf32-round all MMA weights (after pack_w1)
__global__ void round_w_kernel(const float* __restrict__ ew2,
                               const float* __restrict__ nw1,
                               const float* __restrict__ nw2) {
    int i = blockIdx.x * 256 + threadIdx.x;   // 0..163839
    if (i < 32768)        g_ew2r[i] = f2tf32f(ew2[i]);
    else if (i < 98304)   g_nw1r[i - 32768] = f2tf32f(nw1[i - 32768]);
    else if (i < 131072)  g_nw2r[i - 98304] = f2tf32f(nw2[i - 98304]);
    else if (i < 147456)  g_w1ar[i - 131072] = f2tf32f((&g_w1a[1][0][0])[i - 131072]);
    else if (i < 163840)  g_w1br[i - 147456] = f2tf32f((&g_w1b[1][0][0])[i - 147456]);
}

// warp-per-node CSR build (deterministic edge order preserved)
__global__ void deg_kernel() {
    __shared__ int ss[EEv];
    int t = threadIdx.x;
    for (int i = t; i < EEv; i += 256) ss[i] = g_src[i];
    __syncthreads();
    int lane = t & 31;
    int n = blockIdx.x * 8 + (t >> 5);
    int cnt = 0;
    for (int base = 0; base < EEv; base += 32) {
        int v = ss[base + lane];
        cnt += __popc(__ballot_sync(0xffffffffu, v == n));
    }
    if (lane == 0) g_deg[n] = cnt;
}

__global__ void scan_kernel() {
    __shared__ int s[NQv];
    int t = threadIdx.x;
    s[t] = g_deg[t];
    __syncthreads();
    for (int off = 1; off < NQv; off <<= 1) {
        int v = (t >= off) ? s[t - off] : 0;
        __syncthreads();
        s[t] += v;
        __syncthreads();
    }
    g_rowptr[t + 1] = s[t];
    if (t == 0) g_rowptr[0] = 0;
}

__global__ void fill_kernel(const float* __restrict__ eattr) {
    __shared__ int ss[EEv];
    int t = threadIdx.x;
    for (int i = t; i < EEv; i += 256) ss[i] = g_src[i];
    __syncthreads();
    int lane = t & 31;
    int n = blockIdx.x * 8 + (t >> 5);
    int pos = g_rowptr[n];
    for (int base = 0; base < EEv; base += 32) {
        int v = ss[base + lane];
        unsigned m = __ballot_sync(0xffffffffu, v == n);
        if (v == n) {
            int ofs = __popc(m & ((1u << lane) - 1u));
            g_csr_tgt[pos + ofs] = g_tgt[base + lane];
            g_csr_ea[pos + ofs]  = eattr[base + lane];
        }
        pos += __popc(m);
    }
}

// ---------------- round-0 base (exact fp32, one tiny block) ------------------
__global__ __launch_bounds__(256) void base_kernel(
    const float* __restrict__ z0, const float* __restrict__ eb1)
{
    __shared__ __align__(16) float zs[64][LLv];     // 32 KB
    __shared__ float Ws[16 * 129];                  // 8.25 KB
    int t = threadIdx.x;
    const float4* zp = (const float4*)z0;
    float4* sp = (float4*)&zs[0][0];
#pragma unroll
    for (int i = 0; i < 8; i++) sp[t + i * 256] = zp[t + i * 256];
    __syncthreads();

    int cl = t & 31, rg = t >> 5;
    float acc[8][4];
#pragma unroll
    for (int j = 0; j < 8; j++)
#pragma unroll
        for (int cb = 0; cb < 4; cb++) acc[j][cb] = 0.f;

#pragma unroll 1
    for (int kk = 0; kk < 128; kk += 16) {
        __syncthreads();
#pragma unroll
        for (int rep = 0; rep < 2; rep++) {
            int idx = rep * 256 + t;
            int c = idx >> 2, p = (idx & 3) * 4;
            float4 v = *(const float4*)&g_w1ab[c * 128 + kk + p];
            Ws[(p + 0) * 129 + c] = v.x;
            Ws[(p + 1) * 129 + c] = v.y;
            Ws[(p + 2) * 129 + c] = v.z;
            Ws[(p + 3) * 129 + c] = v.w;
        }
        __syncthreads();
#pragma unroll
        for (int kq = 0; kq < 16; kq++) {
            float w0 = Ws[kq * 129 + cl];
            float w1 = Ws[kq * 129 + cl + 32];
            float w2 = Ws[kq * 129 + cl + 64];
            float w3 = Ws[kq * 129 + cl + 96];
#pragma unroll
            for (int j = 0; j < 8; j++) {
                float x = zs[rg * 8 + j][kk + kq];
                acc[j][0] = fmaf(x, w0, acc[j][0]);
                acc[j][1] = fmaf(x, w1, acc[j][1]);
                acc[j][2] = fmaf(x, w2, acc[j][2]);
                acc[j][3] = fmaf(x, w3, acc[j][3]);
            }
        }
    }
#pragma unroll
    for (int cb = 0; cb < 4; cb++) {
        int c = cl + 32 * cb;
        float bi = eb1[c];
#pragma unroll
        for (int j = 0; j < 8; j++)
            g_base[(rg * 8 + j) * LLv + c] = acc[j][cb] + bi;
    }
}

// ---------------- round-1 per-node projections (tf32 MMA) --------------------
// smem: Xh [64][132] + Ws [128][68]
#define PJ_SMEM ((64 * 132 + 128 * WSS) * 4)
__global__ __launch_bounds__(256) void proj_kernel(const float* __restrict__ eb1) {
    extern __shared__ float sm[];
    float* Xh = sm;                 // [64][132], tf32-rounded h
    float* Ws = sm + 64 * 132;

    int r0 = blockIdx.x * 64, t = threadIdx.x;
    int lane = t & 31, w = t >> 5;
    int g = lane >> 2, tig = lane & 3;
    int wm = w & 1, wn = w >> 1;

    // load + round h rows
#pragma unroll
    for (int i = 0; i < 8; i++) {
        int idx = i * 256 + t;                 // float4 units over 64x128
        int r = idx >> 5, j4 = idx & 31;
        float4 v = ((const float4*)(g_h + (r0 + r) * LLv))[j4];
        float* d = &Xh[r * 132 + j4 * 4];
        d[0] = f2tf32f(v.x); d[1] = f2tf32f(v.y);
        d[2] = f2tf32f(v.z); d[3] = f2tf32f(v.w);
    }

    float c[2][4][4];

    mma_gemm64<128>(c, Xh, 132, g_w1ar, Ws, t);
#pragma unroll
    for (int mr = 0; mr < 2; mr++)
#pragma unroll
        for (int nf = 0; nf < 4; nf++)
#pragma unroll
            for (int i = 0; i < 4; i++) {
                int row = wm * 32 + mr * 16 + g + (i >> 1) * 8;
                int col = wn * 32 + nf * 8 + 2 * tig + (i & 1);
                g_A[(r0 + row) * LLv + col] = c[mr][nf][i] + eb1[col];
            }

    mma_gemm64<128>(c, Xh, 132, g_w1br, Ws, t);
#pragma unroll
    for (int mr = 0; mr < 2; mr++)
#pragma unroll
        for (int nf = 0; nf < 4; nf++)
#pragma unroll
            for (int i = 0; i < 4; i++) {
                int row = wm * 32 + mr * 16 + g + (i >> 1) * 8;
                int col = wn * 32 + nf * 8 + 2 * tig + (i & 1);
                g_Bv[(r0 + row) * LLv + col] = c[mr][nf][i];
            }
}

// ---------------- fully fused per-round node kernel (tf32 MMA) ---------------
// smem: inp [64][260] | xs [64][132] | Ws [128][68] | rp [72]
#define RK_FLOATS (64 * 260 + 64 * 132 + 128 * WSS + 72)
#define RK_SMEM (RK_FLOATS * 4)
__global__ __launch_bounds__(256) void round_kernel(
    const float* __restrict__ z0,
    const float* __restrict__ eb2,
    const float* __restrict__ nb1,
    const float* __restrict__ lng, const float* __restrict__ lnb,
    const float* __restrict__ nb2,
    int k)
{
    extern __shared__ float sm[];
    float* inp = sm;                        // [64][260]: [h_tf32 | m_agg_tf32]
    float* xs  = sm + 64 * 260;             // [64][132]
    float* Ws  = sm + 64 * 260 + 64 * 132;  // [128][68]
    int*   rp  = (int*)(Ws + 128 * WSS);    // [65]

    const float* ew2r = g_ew2r + k * LLv * LLv;
    const float* nw1r = g_nw1r + k * LLv * 256;
    const float* nw2r = g_nw2r + k * LLv * LLv;

    int b = blockIdx.y, q0 = blockIdx.x * 64, t = threadIdx.x;
    int rowbase = (b * NQv + q0) * LLv;
    int lane = t & 31, w = t >> 5;
    int g = lane >> 2, tig = lane & 3;
    int wm = w & 1, wn = w >> 1;

    if (t < 65) rp[t] = g_rowptr[q0 + t];
    __syncthreads();

    // ---- stage 1: hid_agg[n] = sum_{e: src=n} relu(A[n]+B[tgt]+ea*w1c) ----
    {
        float4 w1c4 = ((const float4*)&g_w1c[k][0])[lane];
#pragma unroll
        for (int j = 0; j < 8; j++) {
            int r = w * 8 + j;
            float4 a4;
            if (k == 0) a4 = ((const float4*)(g_base + b * LLv))[lane];
            else        a4 = ((const float4*)(g_A + rowbase + r * LLv))[lane];
            float4 acc = make_float4(0.f, 0.f, 0.f, 0.f);
            int e0 = rp[r], e1 = rp[r + 1];
            if (k == 0) {
                for (int e = e0; e < e1; e++) {
                    float ea = g_csr_ea[e];
                    acc.x += fmaxf(fmaf(ea, w1c4.x, a4.x), 0.f);
                    acc.y += fmaxf(fmaf(ea, w1c4.y, a4.y), 0.f);
                    acc.z += fmaxf(fmaf(ea, w1c4.z, a4.z), 0.f);
                    acc.w += fmaxf(fmaf(ea, w1c4.w, a4.w), 0.f);
                }
            } else {
                for (int e = e0; e < e1; e++) {
                    float ea = g_csr_ea[e];
                    int tg = g_csr_tgt[e];
                    float4 bv = ((const float4*)(g_Bv + (b * NQv + tg) * LLv))[lane];
                    acc.x += fmaxf(fmaf(ea, w1c4.x, a4.x + bv.x), 0.f);
                    acc.y += fmaxf(fmaf(ea, w1c4.y, a4.y + bv.y), 0.f);
                    acc.z += fmaxf(fmaf(ea, w1c4.z, a4.z + bv.z), 0.f);
                    acc.w += fmaxf(fmaf(ea, w1c4.w, a4.w + bv.w), 0.f);
                }
            }
            float* d = &xs[r * 132 + lane * 4];
            d[0] = f2tf32f(acc.x); d[1] = f2tf32f(acc.y);
            d[2] = f2tf32f(acc.z); d[3] = f2tf32f(acc.w);
        }
    }

    float c[2][4][4];

    // ---- stage 2: m_agg = hid_agg @ W2^T + deg*b2 -> inp cols 128..255 ----
    mma_gemm64<128>(c, xs, 132, ew2r, Ws, t);
#pragma unroll
    for (int mr = 0; mr < 2; mr++)
#pragma unroll
        for (int nf = 0; nf < 4; nf++)
#pragma unroll
            for (int i = 0; i < 4; i++) {
                int row = wm * 32 + mr * 16 + g + (i >> 1) * 8;
                int col = wn * 32 + nf * 8 + 2 * tig + (i & 1);
                float dg = (float)(rp[row + 1] - rp[row]);
                inp[row * 260 + 128 + col] =
                    f2tf32f(c[mr][nf][i] + dg * eb2[col]);
            }

    // ---- stage 2b: h rows (rounded) into inp cols 0..127 ----
#pragma unroll
    for (int i = 0; i < 8; i++) {
        int idx = i * 256 + t;
        int r = idx >> 5, j4 = idx & 31;
        float4 v = (k == 0) ? ((const float4*)(z0 + b * LLv))[j4]
                            : ((const float4*)(g_h + rowbase + r * LLv))[j4];
        float* d = &inp[r * 260 + j4 * 4];
        d[0] = f2tf32f(v.x); d[1] = f2tf32f(v.y);
        d[2] = f2tf32f(v.z); d[3] = f2tf32f(v.w);
    }

    // ---- stage 3: x = relu([h|m_agg] @ nw1^T + nb1) -> xs (fp32) ----
    mma_gemm64<256>(c, inp, 260, nw1r, Ws, t);
#pragma unroll
    for (int mr = 0; mr < 2; mr++)
#pragma unroll
        for (int nf = 0; nf < 4; nf++)
#pragma unroll
            for (int i = 0; i < 4; i++) {
                int row = wm * 32 + mr * 16 + g + (i >> 1) * 8;
                int col = wn * 32 + nf * 8 + 2 * tig + (i & 1);
                xs[row * 132 + col] = fmaxf(c[mr][nf][i] + nb1[col], 0.f);
            }
    __syncthreads();

    // ---- stage 4: LayerNorm (fp32 stats), write tf32-rounded ----
    {
#pragma unroll
        for (int j = 0; j < 8; j++) {
            int q = w * 8 + j;
            float v0 = xs[q * 132 + lane],      v1 = xs[q * 132 + lane + 32];
            float v2 = xs[q * 132 + lane + 64], v3 = xs[q * 132 + lane + 96];
            float s = v0 + v1 + v2 + v3;
#pragma unroll
            for (int o = 16; o; o >>= 1) s += __shfl_xor_sync(0xffffffffu, s, o);
            float mu = s * (1.f / 128.f);
            float d0 = v0 - mu, d1 = v1 - mu, d2 = v2 - mu, d3 = v3 - mu;
            float s2 = d0 * d0 + d1 * d1 + d2 * d2 + d3 * d3;
#pragma unroll
            for (int o = 16; o; o >>= 1) s2 += __shfl_xor_sync(0xffffffffu, s2, o);
            float rstd = rsqrtf(s2 * (1.f / 128.f) + 1e-5f);
            xs[q * 132 + lane] =
                f2tf32f(d0 * rstd * lng[lane] + lnb[lane]);
            xs[q * 132 + lane + 32] =
                f2tf32f(d1 * rstd * lng[lane + 32] + lnb[lane + 32]);
            xs[q * 132 + lane + 64] =
                f2tf32f(d2 * rstd * lng[lane + 64] + lnb[lane + 64]);
            xs[q * 132 + lane + 96] =
                f2tf32f(d3 * rstd * lng[lane + 96] + lnb[lane + 96]);
        }
    }

    // ---- stage 5: h = xs @ nw2^T + nb2 + h (residual exact from global) ----
    mma_gemm64<128>(c, xs, 132, nw2r, Ws, t);
#pragma unroll
    for (int mr = 0; mr < 2; mr++)
#pragma unroll
        for (int nf = 0; nf < 4; nf++)
#pragma unroll
            for (int i = 0; i < 4; i++) {
                int row = wm * 32 + mr * 16 + g + (i >> 1) * 8;
                int col = wn * 32 + nf * 8 + 2 * tig + (i & 1);
                float res = (k == 0) ? z0[b * LLv + col]
                                     : g_h[rowbase + row * LLv + col];
                g_h[rowbase + row * LLv + col] = res + c[mr][nf][i] + nb2[col];
            }
}

// ---------------- final mean over nodes --------------------------------------
__global__ void mean_kernel(float* __restrict__ out) {
    int b = blockIdx.x, t = threadIdx.x;   // 512 threads
    int l = t & 127, seg = t >> 7;
    const float* p = g_h + (b * NQv + seg * 256) * LLv + l;
    float s = 0.f;
#pragma unroll 8
    for (int q = 0; q < 256; q++) s += p[q * LLv];
    __shared__ float red[4][LLv];
    red[seg][l] = s;
    __syncthreads();
    if (seg == 0)
        out[b * LLv + l] =
            (red[0][l] + red[1][l] + red[2][l] + red[3][l]) * (1.f / 1024.f);
}

// ---------------- launch ------------------------------------------------------
extern "C" void kernel_launch(void* const* d_in, const int* in_sizes, int n_in,
                              void* d_out, int out_size) {
    const float* z0    = (const float*)d_in[0];
    const void*  eidx  = d_in[1];
    const float* eattr = (const float*)d_in[2];
    const float* ew1 = (const float*)d_in[4];
    const float* eb1 = (const float*)d_in[5];
    const float* ew2 = (const float*)d_in[6];
    const float* eb2 = (const float*)d_in[7];
    const float* nw1 = (const float*)d_in[8];
    const float* nb1 = (const float*)d_in[9];
    const float* lng = (const float*)d_in[10];
    const float* lnb = (const float*)d_in[11];
    const float* nw2 = (const float*)d_in[12];
    const float* nb2 = (const float*)d_in[13];
    float* out = (float*)d_out;

    cudaFuncSetAttribute(round_kernel,
        cudaFuncAttributeMaxDynamicSharedMemorySize, RK_SMEM);
    cudaFuncSetAttribute(proj_kernel,
        cudaFuncAttributeMaxDynamicSharedMemorySize, PJ_SMEM);

    detect_idx_kernel<<<1, 1>>>(eidx);
    cvt_idx_kernel<<<(2 * EEv + 255) / 256, 256>>>(eidx);
    pack_w1_kernel<<<(2 * LLv * 257 + 255) / 256, 256>>>(ew1);
    sum_w_kernel<<<LLv * LLv / 256, 256>>>();
    round_w_kernel<<<640, 256>>>(ew2, nw1, nw2);
    deg_kernel<<<NQv / 8, 256>>>();
    scan_kernel<<<1, NQv>>>();
    fill_kernel<<<NQv / 8, 256>>>(eattr);

    base_kernel<<<1, 256>>>(z0, eb1);
    round_kernel<<<dim3(NQv / 64, BB), 256, RK_SMEM>>>(
        z0, eb2, nb1, lng, lnb, nb2, 0);

    proj_kernel<<<BB * NQv / 64, 256, PJ_SMEM>>>(eb1 + 128);
    round_kernel<<<dim3(NQv / 64, BB), 256, RK_SMEM>>>(
        z0, eb2 + LLv, nb1 + LLv,
        lng + LLv, lnb + LLv, nb2 + LLv, 1);

    mean_kernel<<<BB, 512>>>(out);
}

// round 5
// speedup vs baseline: 9.0823x; 1.0520x over previous
#include <cuda_runtime.h>

#define BB 64
#define NQv 1024
#define LLv 128
#define EEv 8192

// ---------------- scratch (static device globals; no allocations) ----------
__device__ float g_h[BB * NQv * LLv];      // node states (exact fp32)
__device__ float g_A[BB * NQv * LLv];      // h @ W1a^T + b1   (round 1)
__device__ float g_Bv[BB * NQv * LLv];     // h @ W1b^T        (round 1)
__device__ float g_base[BB * LLv];         // round-0 collapsed layer-1
__device__ float g_w1a[2][LLv][LLv];       // packed e_w1[:, :, 0:128]
__device__ float g_w1b[2][LLv][LLv];       // packed e_w1[:, :, 128:256]
__device__ float g_w1ab[LLv * LLv];        // w1a[0]+w1b[0]
__device__ float g_w1c[2][LLv];            // packed e_w1[:, :, 256]
// fragment-packed tf32 weights: per matrix [K/64 chunks][kg8][cg16][g8][tig4]x2
__device__ float g_pw1a[16384], g_pw1b[16384];
__device__ float g_pew2[2][16384];
__device__ float g_pnw1[2][32768];
__device__ float g_pnw2[2][16384];
__device__ int   g_src[EEv];
__device__ int   g_tgt[EEv];
__device__ int   g_rowptr[NQv + 1];
__device__ int   g_csr_tgt[EEv];
__device__ float g_csr_ea[EEv];
__device__ int   g_is64;

// ---------------- tf32 / mma helpers ----------------------------------------
__device__ __forceinline__ float f2tf32f(float x) {
    unsigned r;
    asm("cvt.rna.tf32.f32 %0, %1;" : "=r"(r) : "f"(x));
    return __uint_as_float(r);
}
__device__ __forceinline__ void mma_tf32(float (&c)[4],
    unsigned a0, unsigned a1, unsigned a2, unsigned a3,
    unsigned b0, unsigned b1)
{
    asm volatile(
        "mma.sync.aligned.m16n8k8.row.col.f32.tf32.tf32.f32 "
        "{%0,%1,%2,%3}, {%4,%5,%6,%7}, {%8,%9}, {%0,%1,%2,%3};"
        : "+f"(c[0]), "+f"(c[1]), "+f"(c[2]), "+f"(c[3])
        : "r"(a0), "r"(a1), "r"(a2), "r"(a3), "r"(b0), "r"(b1));
}
__device__ __forceinline__ void zacc(float (&c)[2][4][4]) {
#pragma unroll
    for (int a = 0; a < 2; a++)
#pragma unroll
        for (int b = 0; b < 4; b++)
#pragma unroll
            for (int i = 0; i < 4; i++) c[a][b][i] = 0.f;
}

// chunk = 8192 floats (64 k x 128 cols, fragment-packed). 256 threads.
__device__ __forceinline__ void wload(const float* Wp, float4 (&wv)[8], int t) {
    const float4* p = (const float4*)Wp;
#pragma unroll
    for (int i = 0; i < 8; i++) wv[i] = p[t + i * 256];
}
__device__ __forceinline__ void wstore(float* buf, const float4 (&wv)[8], int t) {
    float4* p = (float4*)buf;
#pragma unroll
    for (int i = 0; i < 8; i++) p[t + i * 256] = wv[i];
}

// one 64-k chunk of C[64][128] += Xs[64][K-slice] @ W^T, warp (wm,wn) 32x32 tile
template<int XST>
__device__ __forceinline__ void compute_chunk(
    float (&c)[2][4][4], const float* Xs, int kkbase,
    const float* buf, int lane, int wm, int wn)
{
    int g = lane >> 2, tig = lane & 3;
    const float2* bf = (const float2*)buf;
#pragma unroll
    for (int ks = 0; ks < 8; ks++) {
        unsigned a[2][4];
#pragma unroll
        for (int mr = 0; mr < 2; mr++) {
            const float* xr  = Xs + (wm * 32 + mr * 16 + g) * XST + kkbase + ks * 8;
            const float* xr8 = xr + 8 * XST;
            a[mr][0] = __float_as_uint(xr[tig]);
            a[mr][1] = __float_as_uint(xr8[tig]);
            a[mr][2] = __float_as_uint(xr[tig + 4]);
            a[mr][3] = __float_as_uint(xr8[tig + 4]);
        }
#pragma unroll
        for (int nf = 0; nf < 4; nf++) {
            float2 bb = bf[(ks * 16 + wn * 4 + nf) * 32 + g * 4 + tig];
#pragma unroll
            for (int mr = 0; mr < 2; mr++)
                mma_tf32(c[mr][nf], a[mr][0], a[mr][1], a[mr][2], a[mr][3],
                         __float_as_uint(bb.x), __float_as_uint(bb.y));
        }
    }
}
// acc (mr,nf,i): row = wm*32+mr*16+g+(i>>1)*8, col = wn*32+nf*8+2*tig+(i&1)

// ---------------- merged setup (1 block x 1024) -------------------------------
__global__ void setup_kernel(const void* __restrict__ eidx,
                             const float* __restrict__ ew1) {
    __shared__ int sflag;
    __shared__ int sdeg[NQv];
    int t = threadIdx.x;
    if (t == 0) {
        const long long* p = (const long long*)eidx;
        int ok = 1;
        for (int i = 0; i < 64; i++) {
            long long v = p[i];
            if (v < 0 || v >= NQv) { ok = 0; break; }
        }
        sflag = ok; g_is64 = ok;
    }
    __syncthreads();
    int is64 = sflag;
    for (int i = t; i < 2 * EEv; i += 1024) {
        int v = is64 ? (int)((const long long*)eidx)[i] : ((const int*)eidx)[i];
        if (i < EEv) g_src[i] = v;
        else         g_tgt[i - EEv] = v;
    }
    for (int idx = t; idx < 2 * LLv * 257; idx += 1024) {
        int k = idx / (LLv * 257);
        int rem = idx % (LLv * 257);
        int c = rem / 257, j = rem % 257;
        float v = ew1[idx];
        if (j < 128)      g_w1a[k][c][j]       = v;
        else if (j < 256) g_w1b[k][c][j - 128] = v;
        else              g_w1c[k][c]          = v;
    }
    __syncthreads();
    for (int i = t; i < LLv * LLv; i += 1024)
        g_w1ab[i] = (&g_w1a[0][0][0])[i] + (&g_w1b[0][0][0])[i];
    sdeg[t] = 0;
    __syncthreads();
    for (int e = t; e < EEv; e += 1024) atomicAdd(&sdeg[g_src[e]], 1);
    __syncthreads();
    for (int off = 1; off < NQv; off <<= 1) {
        int v = (t >= off) ? sdeg[t - off] : 0;
        __syncthreads();
        sdeg[t] += v;
        __syncthreads();
    }
    g_rowptr[t + 1] = sdeg[t];
    if (t == 0) g_rowptr[0] = 0;
}

// deterministic CSR fill (warp-per-node, order-preserving)
__global__ void fill_kernel(const float* __restrict__ eattr) {   // NQv/8 x 256
    __shared__ int ss[EEv];
    int t = threadIdx.x;
    for (int i = t; i < EEv; i += 256) ss[i] = g_src[i];
    __syncthreads();
    int lane = t & 31;
    int n = blockIdx.x * 8 + (t >> 5);
    int pos = g_rowptr[n];
    for (int base = 0; base < EEv; base += 32) {
        int v = ss[base + lane];
        unsigned m = __ballot_sync(0xffffffffu, v == n);
        if (v == n) {
            int ofs = __popc(m & ((1u << lane) - 1u));
            g_csr_tgt[pos + ofs] = g_tgt[base + lane];
            g_csr_ea[pos + ofs]  = eattr[base + lane];
        }
        pos += __popc(m);
    }
}

// fragment-pack + tf32-round all MMA weights
__global__ void repack_kernel(const float* __restrict__ ew2,
                              const float* __restrict__ nw1,
                              const float* __restrict__ nw2) {
    int i = blockIdx.x * 256 + threadIdx.x;   // < 163840
    const float* src; float* dst; int K, j;
    if (i < 16384)       { src = &g_w1a[1][0][0]; dst = g_pw1a; K = 128; j = i; }
    else if (i < 32768)  { src = &g_w1b[1][0][0]; dst = g_pw1b; K = 128; j = i - 16384; }
    else if (i < 65536)  { int kk = (i - 32768) >> 14; src = ew2 + kk * 16384;
                           dst = g_pew2[kk]; K = 128; j = (i - 32768) & 16383; }
    else if (i < 131072) { int kk = (i - 65536) >> 15; src = nw1 + kk * 32768;
                           dst = g_pnw1[kk]; K = 256; j = (i - 65536) & 32767; }
    else                 { int kk = (i - 131072) >> 14; src = nw2 + kk * 16384;
                           dst = g_pnw2[kk]; K = 128; j = (i - 131072) & 16383; }
    int p = j & 1, tig = (j >> 1) & 3, g = (j >> 3) & 7;
    int cg = (j >> 6) & 15, kg = (j >> 10) & 7, ck = j >> 13;
    int row = cg * 8 + g;
    int k = ck * 64 + kg * 8 + tig + 4 * p;
    dst[j] = f2tf32f(src[row * K + k]);
}

// ---------------- round-0 base (exact fp32, 4 blocks x 16 rows) ---------------
__global__ __launch_bounds__(256) void base_kernel(
    const float* __restrict__ z0, const float* __restrict__ eb1)
{
    __shared__ __align__(16) float zs[16][LLv];
    __shared__ float Ws[16 * 129];
    int t = threadIdx.x, r0 = blockIdx.x * 16;
    const float4* zp = (const float4*)(z0 + r0 * LLv);
    float4* sp = (float4*)&zs[0][0];
#pragma unroll
    for (int i = 0; i < 2; i++) sp[t + i * 256] = zp[t + i * 256];
    __syncthreads();

    int cl = t & 31, rg = t >> 5;
    float acc[2][4];
#pragma unroll
    for (int j = 0; j < 2; j++)
#pragma unroll
        for (int cb = 0; cb < 4; cb++) acc[j][cb] = 0.f;

#pragma unroll 1
    for (int kk = 0; kk < 128; kk += 16) {
        __syncthreads();
#pragma unroll
        for (int rep = 0; rep < 2; rep++) {
            int idx = rep * 256 + t;
            int c = idx >> 2, p = (idx & 3) * 4;
            float4 v = *(const float4*)&g_w1ab[c * 128 + kk + p];
            Ws[(p + 0) * 129 + c] = v.x;
            Ws[(p + 1) * 129 + c] = v.y;
            Ws[(p + 2) * 129 + c] = v.z;
            Ws[(p + 3) * 129 + c] = v.w;
        }
        __syncthreads();
#pragma unroll
        for (int kq = 0; kq < 16; kq++) {
            float w0 = Ws[kq * 129 + cl];
            float w1 = Ws[kq * 129 + cl + 32];
            float w2 = Ws[kq * 129 + cl + 64];
            float w3 = Ws[kq * 129 + cl + 96];
#pragma unroll
            for (int j = 0; j < 2; j++) {
                float x = zs[rg * 2 + j][kk + kq];
                acc[j][0] = fmaf(x, w0, acc[j][0]);
                acc[j][1] = fmaf(x, w1, acc[j][1]);
                acc[j][2] = fmaf(x, w2, acc[j][2]);
                acc[j][3] = fmaf(x, w3, acc[j][3]);
            }
        }
    }
#pragma unroll
    for (int cb = 0; cb < 4; cb++) {
        int c = cl + 32 * cb;
        float bi = eb1[c];
#pragma unroll
        for (int j = 0; j < 2; j++)
            g_base[(r0 + rg * 2 + j) * LLv + c] = acc[j][cb] + bi;
    }
}

// ---------------- round-1 per-node projections (pipelined tf32 MMA) ----------
#define PJ_SMEM ((64 * 132 + 2 * 8192) * 4)
__global__ __launch_bounds__(256) void proj_kernel(const float* __restrict__ eb1) {
    extern __shared__ float sm[];
    float* Xh  = sm;                 // [64][132]
    float* wb0 = sm + 64 * 132;
    float* wb1 = wb0 + 8192;

    int r0 = blockIdx.x * 64, t = threadIdx.x;
    int lane = t & 31, w = t >> 5;
    int g = lane >> 2, tig = lane & 3;
    int wm = w & 1, wn = w >> 1;

    float4 wv[8];
    wload(g_pw1a, wv, t);
#pragma unroll
    for (int i = 0; i < 8; i++) {
        int idx = i * 256 + t;
        int r = idx >> 5, j4 = idx & 31;
        float4 v = ((const float4*)(g_h + (r0 + r) * LLv))[j4];
        float* d = &Xh[r * 132 + j4 * 4];
        d[0] = f2tf32f(v.x); d[1] = f2tf32f(v.y);
        d[2] = f2tf32f(v.z); d[3] = f2tf32f(v.w);
    }
    wstore(wb0, wv, t);
    __syncthreads();

    float c[2][4][4];
    zacc(c);
    wload(g_pw1a + 8192, wv, t);
    compute_chunk<132>(c, Xh, 0, wb0, lane, wm, wn);
    wstore(wb1, wv, t);
    __syncthreads();
    wload(g_pw1b, wv, t);
    compute_chunk<132>(c, Xh, 64, wb1, lane, wm, wn);
    wstore(wb0, wv, t);
#pragma unroll
    for (int mr = 0; mr < 2; mr++)
#pragma unroll
        for (int nf = 0; nf < 4; nf++)
#pragma unroll
            for (int i = 0; i < 4; i++) {
                int row = wm * 32 + mr * 16 + g + (i >> 1) * 8;
                int col = wn * 32 + nf * 8 + 2 * tig + (i & 1);
                g_A[(r0 + row) * LLv + col] = c[mr][nf][i] + eb1[col];
            }
    __syncthreads();

    zacc(c);
    wload(g_pw1b + 8192, wv, t);
    compute_chunk<132>(c, Xh, 0, wb0, lane, wm, wn);
    wstore(wb1, wv, t);
    __syncthreads();
    compute_chunk<132>(c, Xh, 64, wb1, lane, wm, wn);
#pragma unroll
    for (int mr = 0; mr < 2; mr++)
#pragma unroll
        for (int nf = 0; nf < 4; nf++)
#pragma unroll
            for (int i = 0; i < 4; i++) {
                int row = wm * 32 + mr * 16 + g + (i >> 1) * 8;
                int col = wn * 32 + nf * 8 + 2 * tig + (i & 1);
                g_Bv[(r0 + row) * LLv + col] = c[mr][nf][i];
            }
}

// ---------------- fully fused per-round node kernel (pipelined tf32 MMA) -----
// smem floats: inp 16640 | xs 8448 | wb0 8192 | wb1 8192 | ea 1024 | tgt 1024 | rp 68
#define RK_SMEM ((16640 + 8448 + 8192 + 8192 + 1024 + 1024 + 68) * 4)
__global__ __launch_bounds__(256) void round_kernel(
    const float* __restrict__ z0,
    const float* __restrict__ eb2,
    const float* __restrict__ nb1,
    const float* __restrict__ lng, const float* __restrict__ lnb,
    const float* __restrict__ nb2,
    int k)
{
    extern __shared__ float sm[];
    float* inp   = sm;                       // [64][260]: [h_tf32 | m_agg_tf32]
    float* xs    = sm + 16640;               // [64][132]
    float* wb0   = sm + 16640 + 8448;
    float* wb1   = wb0 + 8192;
    float* es_ea = wb1 + 8192;               // [1024]
    int*   es_tg = (int*)(es_ea + 1024);     // [1024]
    int*   rp    = (int*)(es_ea + 2048);     // [65]

    const float* pew2 = g_pew2[k];
    const float* pnw1 = g_pnw1[k];
    const float* pnw2 = g_pnw2[k];

    int b = blockIdx.y, q0 = blockIdx.x * 64, t = threadIdx.x;
    int rowbase = (b * NQv + q0) * LLv;
    int lane = t & 31, w = t >> 5;
    int g = lane >> 2, tig = lane & 3;
    int wm = w & 1, wn = w >> 1;

    if (t < 65) rp[t] = g_rowptr[q0 + t];
    __syncthreads();

    float4 wv[8];
    wload(pew2, wv, t);                      // prefetch GEMM1 chunk0

    // block-local CSR prefetch
    int e0b = rp[0];
    int cnt = rp[64] - e0b;
    bool insm = (cnt <= 1024);
    if (insm) {
        for (int i = t; i < cnt; i += 256) {
            es_tg[i] = g_csr_tgt[e0b + i];
            es_ea[i] = g_csr_ea[e0b + i];
        }
    }
    __syncthreads();
    const int*   tgp = insm ? es_tg : g_csr_tgt;
    const float* eap = insm ? es_ea : g_csr_ea;
    int ebias = insm ? e0b : 0;

    // ---- stage 1: hid_agg[n] = sum_{e: src=n} relu(A[n]+B[tgt]+ea*w1c) ----
    {
        float4 w1c4 = ((const float4*)&g_w1c[k][0])[lane];
#pragma unroll
        for (int j = 0; j < 8; j++) {
            int r = w * 8 + j;
            float4 a4;
            if (k == 0) a4 = ((const float4*)(g_base + b * LLv))[lane];
            else        a4 = ((const float4*)(g_A + rowbase + r * LLv))[lane];
            float4 acc = make_float4(0.f, 0.f, 0.f, 0.f);
            int e0 = rp[r] - ebias, e1 = rp[r + 1] - ebias;
            if (k == 0) {
                for (int e = e0; e < e1; e++) {
                    float ea = eap[e];
                    acc.x += fmaxf(fmaf(ea, w1c4.x, a4.x), 0.f);
                    acc.y += fmaxf(fmaf(ea, w1c4.y, a4.y), 0.f);
                    acc.z += fmaxf(fmaf(ea, w1c4.z, a4.z), 0.f);
                    acc.w += fmaxf(fmaf(ea, w1c4.w, a4.w), 0.f);
                }
            } else {
                for (int e = e0; e < e1; e++) {
                    float ea = eap[e];
                    int tg = tgp[e];
                    float4 bv = ((const float4*)(g_Bv + (b * NQv + tg) * LLv))[lane];
                    acc.x += fmaxf(fmaf(ea, w1c4.x, a4.x + bv.x), 0.f);
                    acc.y += fmaxf(fmaf(ea, w1c4.y, a4.y + bv.y), 0.f);
                    acc.z += fmaxf(fmaf(ea, w1c4.z, a4.z + bv.z), 0.f);
                    acc.w += fmaxf(fmaf(ea, w1c4.w, a4.w + bv.w), 0.f);
                }
            }
            float* d = &xs[r * 132 + lane * 4];
            d[0] = f2tf32f(acc.x); d[1] = f2tf32f(acc.y);
            d[2] = f2tf32f(acc.z); d[3] = f2tf32f(acc.w);
        }
    }
    wstore(wb0, wv, t);
    __syncthreads();                          // xs + wb0 ready

    float c[2][4][4];

    // ---- GEMM1: m_agg = hid_agg @ W2^T + deg*b2 ----
    zacc(c);
    wload(pew2 + 8192, wv, t);
    compute_chunk<132>(c, xs, 0, wb0, lane, wm, wn);
    wstore(wb1, wv, t);
    __syncthreads();
    wload(pnw1, wv, t);
    compute_chunk<132>(c, xs, 64, wb1, lane, wm, wn);
    wstore(wb0, wv, t);

    // h residual loads overlap epilogue
    float4 hr[8];
#pragma unroll
    for (int i = 0; i < 8; i++) {
        int idx = i * 256 + t;
        int r = idx >> 5, j4 = idx & 31;
        hr[i] = (k == 0) ? ((const float4*)(z0 + b * LLv))[j4]
                         : ((const float4*)(g_h + rowbase + r * LLv))[j4];
    }
#pragma unroll
    for (int mr = 0; mr < 2; mr++)
#pragma unroll
        for (int nf = 0; nf < 4; nf++)
#pragma unroll
            for (int i = 0; i < 4; i++) {
                int row = wm * 32 + mr * 16 + g + (i >> 1) * 8;
                int col = wn * 32 + nf * 8 + 2 * tig + (i & 1);
                float dg = (float)(rp[row + 1] - rp[row]);
                inp[row * 260 + 128 + col] = f2tf32f(c[mr][nf][i] + dg * eb2[col]);
            }
#pragma unroll
    for (int i = 0; i < 8; i++) {
        int idx = i * 256 + t;
        int r = idx >> 5, j4 = idx & 31;
        float* d = &inp[r * 260 + j4 * 4];
        d[0] = f2tf32f(hr[i].x); d[1] = f2tf32f(hr[i].y);
        d[2] = f2tf32f(hr[i].z); d[3] = f2tf32f(hr[i].w);
    }
    __syncthreads();                          // inp + wb0 ready

    // ---- GEMM2: x = [h|m_agg] @ nw1^T (K=256, 4 chunks) ----
    zacc(c);
    wload(pnw1 + 8192, wv, t);
    compute_chunk<260>(c, inp, 0, wb0, lane, wm, wn);
    wstore(wb1, wv, t);
    __syncthreads();
    wload(pnw1 + 16384, wv, t);
    compute_chunk<260>(c, inp, 64, wb1, lane, wm, wn);
    wstore(wb0, wv, t);
    __syncthreads();
    wload(pnw1 + 24576, wv, t);
    compute_chunk<260>(c, inp, 128, wb0, lane, wm, wn);
    wstore(wb1, wv, t);
    __syncthreads();
    wload(pnw2, wv, t);
    compute_chunk<260>(c, inp, 192, wb1, lane, wm, wn);
    wstore(wb0, wv, t);
#pragma unroll
    for (int mr = 0; mr < 2; mr++)
#pragma unroll
        for (int nf = 0; nf < 4; nf++)
#pragma unroll
            for (int i = 0; i < 4; i++) {
                int row = wm * 32 + mr * 16 + g + (i >> 1) * 8;
                int col = wn * 32 + nf * 8 + 2 * tig + (i & 1);
                xs[row * 132 + col] = fmaxf(c[mr][nf][i] + nb1[col], 0.f);
            }
    __syncthreads();                          // xs + wb0 ready

    // ---- LayerNorm (fp32 stats), write tf32-rounded ----
#pragma unroll
    for (int j = 0; j < 8; j++) {
        int q = w * 8 + j;
        float v0 = xs[q * 132 + lane],      v1 = xs[q * 132 + lane + 32];
        float v2 = xs[q * 132 + lane + 64], v3 = xs[q * 132 + lane + 96];
        float s = v0 + v1 + v2 + v3;
#pragma unroll
        for (int o = 16; o; o >>= 1) s += __shfl_xor_sync(0xffffffffu, s, o);
        float mu = s * (1.f / 128.f);
        float d0 = v0 - mu, d1 = v1 - mu, d2 = v2 - mu, d3 = v3 - mu;
        float s2 = d0 * d0 + d1 * d1 + d2 * d2 + d3 * d3;
#pragma unroll
        for (int o = 16; o; o >>= 1) s2 += __shfl_xor_sync(0xffffffffu, s2, o);
        float rstd = rsqrtf(s2 * (1.f / 128.f) + 1e-5f);
        xs[q * 132 + lane]      = f2tf32f(d0 * rstd * lng[lane]      + lnb[lane]);
        xs[q * 132 + lane + 32] = f2tf32f(d1 * rstd * lng[lane + 32] + lnb[lane + 32]);
        xs[q * 132 + lane + 64] = f2tf32f(d2 * rstd * lng[lane + 64] + lnb[lane + 64]);
        xs[q * 132 + lane + 96] = f2tf32f(d3 * rstd * lng[lane + 96] + lnb[lane + 96]);
    }
    __syncthreads();

    // ---- GEMM3: h = xs @ nw2^T + nb2 + h ----
    zacc(c);
    wload(pnw2 + 8192, wv, t);
    compute_chunk<132>(c, xs, 0, wb0, lane, wm, wn);
    wstore(wb1, wv, t);
    __syncthreads();
    compute_chunk<132>(c, xs, 64, wb1, lane, wm, wn);
#pragma unroll
    for (int mr = 0; mr < 2; mr++)
#pragma unroll
        for (int nf = 0; nf < 4; nf++)
#pragma unroll
            for (int i = 0; i < 4; i++) {
                int row = wm * 32 + mr * 16 + g + (i >> 1) * 8;
                int col = wn * 32 + nf * 8 + 2 * tig + (i & 1);
                float res = (k == 0) ? z0[b * LLv + col]
                                     : g_h[rowbase + row * LLv + col];
                g_h[rowbase + row * LLv + col] = res + c[mr][nf][i] + nb2[col];
            }
}

// ---------------- final mean over nodes --------------------------------------
__global__ void mean_kernel(float* __restrict__ out) {
    int b = blockIdx.x, t = threadIdx.x;   // 512 threads
    int l = t & 127, seg = t >> 7;
    const float* p = g_h + (b * NQv + seg * 256) * LLv + l;
    float s = 0.f;
#pragma unroll 8
    for (int q = 0; q < 256; q++) s += p[q * LLv];
    __shared__ float red[4][LLv];
    red[seg][l] = s;
    __syncthreads();
    if (seg == 0)
        out[b * LLv + l] =
            (red[0][l] + red[1][l] + red[2][l] + red[3][l]) * (1.f / 1024.f);
}

// ---------------- launch ------------------------------------------------------
extern "C" void kernel_launch(void* const* d_in, const int* in_sizes, int n_in,
                              void* d_out, int out_size) {
    const float* z0    = (const float*)d_in[0];
    const void*  eidx  = d_in[1];
    const float* eattr = (const float*)d_in[2];
    const float* ew1 = (const float*)d_in[4];
    const float* eb1 = (const float*)d_in[5];
    const float* ew2 = (const float*)d_in[6];
    const float* eb2 = (const float*)d_in[7];
    const float* nw1 = (const float*)d_in[8];
    const float* nb1 = (const float*)d_in[9];
    const float* lng = (const float*)d_in[10];
    const float* lnb = (const float*)d_in[11];
    const float* nw2 = (const float*)d_in[12];
    const float* nb2 = (const float*)d_in[13];
    float* out = (float*)d_out;

    cudaFuncSetAttribute(round_kernel,
        cudaFuncAttributeMaxDynamicSharedMemorySize, RK_SMEM);
    cudaFuncSetAttribute(proj_kernel,
        cudaFuncAttributeMaxDynamicSharedMemorySize, PJ_SMEM);

    setup_kernel<<<1, 1024>>>(eidx, ew1);
    fill_kernel<<<NQv / 8, 256>>>(eattr);
    repack_kernel<<<640, 256>>>(ew2, nw1, nw2);

    base_kernel<<<4, 256>>>(z0, eb1);
    round_kernel<<<dim3(NQv / 64, BB), 256, RK_SMEM>>>(
        z0, eb2, nb1, lng, lnb, nb2, 0);

    proj_kernel<<<BB * NQv / 64, 256, PJ_SMEM>>>(eb1 + 128);
    round_kernel<<<dim3(NQv / 64, BB), 256, RK_SMEM>>>(
        z0, eb2 + LLv, nb1 + LLv,
        lng + LLv, lnb + LLv, nb2 + LLv, 1);

    mean_kernel<<<BB, 512>>>(out);
}

// round 6
// speedup vs baseline: 10.7567x; 1.1844x over previous
#include <cuda_runtime.h>

#define BB 64
#define NQv 1024
#define LLv 128
#define EEv 8192

// ---------------- scratch (static device globals; no allocations) ----------
__device__ float g_h[BB * NQv * LLv];      // node states (exact fp32)
__device__ float g_A[BB * NQv * LLv];      // h @ W1a^T + b1   (round 1)
__device__ float g_Bv[BB * NQv * LLv];     // h @ W1b^T        (round 1)
__device__ float g_base[BB * LLv];         // round-0 collapsed layer-1
__device__ float g_w1abT[LLv * LLv];       // (w1a[0]+w1b[0])^T  [k][c]
__device__ float g_w1c[2][LLv];            // e_w1[:, :, 256]
// fragment-packed tf32 weights: [chunk32 of 4096 floats] x K/32
__device__ float g_pw1a[16384], g_pw1b[16384];
__device__ float g_pew2[2][16384];
__device__ float g_pnw1[2][32768];
__device__ float g_pnw2[2][16384];
__device__ int   g_src[EEv];
__device__ int   g_tgt[EEv];
__device__ int   g_rowptr[NQv + 1];
__device__ int   g_csr_tgt[EEv];
__device__ float g_csr_ea[EEv];
__device__ int   g_is64;

// ---------------- tf32 / mma / cp.async helpers ------------------------------
__device__ __forceinline__ float f2tf32f(float x) {
    unsigned r;
    asm("cvt.rna.tf32.f32 %0, %1;" : "=r"(r) : "f"(x));
    return __uint_as_float(r);
}
__device__ __forceinline__ void mma_tf32(float (&c)[4],
    unsigned a0, unsigned a1, unsigned a2, unsigned a3,
    unsigned b0, unsigned b1)
{
    asm volatile(
        "mma.sync.aligned.m16n8k8.row.col.f32.tf32.tf32.f32 "
        "{%0,%1,%2,%3}, {%4,%5,%6,%7}, {%8,%9}, {%0,%1,%2,%3};"
        : "+f"(c[0]), "+f"(c[1]), "+f"(c[2]), "+f"(c[3])
        : "r"(a0), "r"(a1), "r"(a2), "r"(a3), "r"(b0), "r"(b1));
}
__device__ __forceinline__ void zacc(float (&c)[2][4][4]) {
#pragma unroll
    for (int a = 0; a < 2; a++)
#pragma unroll
        for (int b = 0; b < 4; b++)
#pragma unroll
            for (int i = 0; i < 4; i++) c[a][b][i] = 0.f;
}
__device__ __forceinline__ void cpa16(float* dst, const float* src) {
    unsigned d = (unsigned)__cvta_generic_to_shared(dst);
    asm volatile("cp.async.cg.shared.global [%0], [%1], 16;" :: "r"(d), "l"(src));
}
__device__ __forceinline__ void cpa_commit() {
    asm volatile("cp.async.commit_group;" ::: "memory");
}
template<int N> __device__ __forceinline__ void cpa_wait() {
    asm volatile("cp.async.wait_group %0;" :: "n"(N) : "memory");
}
// 32-k weight chunk = 4096 floats, 128 threads x 8 x 16B
__device__ __forceinline__ void pf_chunk(float* buf, const float* Wp, int t) {
#pragma unroll
    for (int i = 0; i < 8; i++)
        cpa16(buf + (i * 128 + t) * 4, Wp + (i * 128 + t) * 4);
    cpa_commit();
}

// one 32-k chunk of C[32][128] += Xs @ W^T; warp wn owns cols [wn*32, +32)
template<int XST>
__device__ __forceinline__ void compute_chunk32(
    float (&c)[2][4][4], const float* Xs, int kkbase,
    const float* buf, int lane, int wn)
{
    int g = lane >> 2, tig = lane & 3;
    const float2* bf = (const float2*)buf;
#pragma unroll
    for (int ks = 0; ks < 4; ks++) {
        unsigned a[2][4];
#pragma unroll
        for (int mr = 0; mr < 2; mr++) {
            const float* xr  = Xs + (mr * 16 + g) * XST + kkbase + ks * 8;
            const float* xr8 = xr + 8 * XST;
            a[mr][0] = __float_as_uint(xr[tig]);
            a[mr][1] = __float_as_uint(xr8[tig]);
            a[mr][2] = __float_as_uint(xr[tig + 4]);
            a[mr][3] = __float_as_uint(xr8[tig + 4]);
        }
#pragma unroll
        for (int nf = 0; nf < 4; nf++) {
            float2 bb = bf[(ks * 16 + wn * 4 + nf) * 32 + g * 4 + tig];
#pragma unroll
            for (int mr = 0; mr < 2; mr++)
                mma_tf32(c[mr][nf], a[mr][0], a[mr][1], a[mr][2], a[mr][3],
                         __float_as_uint(bb.x), __float_as_uint(bb.y));
        }
    }
}
// acc (mr,nf,i): row = mr*16+g+(i>>1)*8, col = wn*32+nf*8+2*tig+(i&1)

// cp.async-pipelined GEMM over nchunk 32-k chunks (entry/exit: 0 pending groups)
template<int XST>
__device__ __forceinline__ void run_gemm(
    float (&c)[2][4][4], const float* Xs, const float* __restrict__ Wp,
    int nchunk, float* wb, int t, int lane, int wn)
{
    zacc(c);
    pf_chunk(wb, Wp, t);
    if (nchunk > 1) pf_chunk(wb + 4096, Wp + 4096, t);
#pragma unroll 1
    for (int ci = 0; ci < nchunk; ci++) {
        if (ci < nchunk - 1) cpa_wait<1>(); else cpa_wait<0>();
        __syncthreads();
        compute_chunk32<XST>(c, Xs, ci * 32, wb + (ci & 1) * 4096, lane, wn);
        __syncthreads();
        if (ci + 2 < nchunk) pf_chunk(wb + (ci & 1) * 4096, Wp + (ci + 2) * 4096, t);
    }
}

// ---------------- setup: edges + degree + scan (1 block x 1024) ---------------
__global__ void setup_kernel(const void* __restrict__ eidx) {
    __shared__ int sflag;
    __shared__ int sdeg[NQv];
    int t = threadIdx.x;
    if (t == 0) {
        const long long* p = (const long long*)eidx;
        int ok = 1;
        for (int i = 0; i < 64; i++) {
            long long v = p[i];
            if (v < 0 || v >= NQv) { ok = 0; break; }
        }
        sflag = ok; g_is64 = ok;
    }
    __syncthreads();
    int is64 = sflag;
    for (int i = t; i < 2 * EEv; i += 1024) {
        int v = is64 ? (int)((const long long*)eidx)[i] : ((const int*)eidx)[i];
        if (i < EEv) g_src[i] = v;
        else         g_tgt[i - EEv] = v;
    }
    sdeg[t] = 0;
    __syncthreads();
    for (int e = t; e < EEv; e += 1024) atomicAdd(&sdeg[g_src[e]], 1);
    __syncthreads();
    for (int off = 1; off < NQv; off <<= 1) {
        int v = (t >= off) ? sdeg[t - off] : 0;
        __syncthreads();
        sdeg[t] += v;
        __syncthreads();
    }
    g_rowptr[t + 1] = sdeg[t];
    if (t == 0) g_rowptr[0] = 0;
}

// deterministic CSR fill (warp-per-node, order-preserving)
__global__ void fill_kernel(const float* __restrict__ eattr) {   // NQv/8 x 256
    __shared__ int ss[EEv];
    int t = threadIdx.x;
    for (int i = t; i < EEv; i += 256) ss[i] = g_src[i];
    __syncthreads();
    int lane = t & 31;
    int n = blockIdx.x * 8 + (t >> 5);
    int pos = g_rowptr[n];
    for (int base = 0; base < EEv; base += 32) {
        int v = ss[base + lane];
        unsigned m = __ballot_sync(0xffffffffu, v == n);
        if (v == n) {
            int ofs = __popc(m & ((1u << lane) - 1u));
            g_csr_tgt[pos + ofs] = g_tgt[base + lane];
            g_csr_ea[pos + ofs]  = eattr[base + lane];
        }
        pos += __popc(m);
    }
}

// fragment-pack + tf32-round weights; also w1abT and w1c (all from raw inputs)
__global__ void repack_kernel(const float* __restrict__ ew1,
                              const float* __restrict__ ew2,
                              const float* __restrict__ nw1,
                              const float* __restrict__ nw2) {
    int i = blockIdx.x * 256 + threadIdx.x;   // < 180480
    if (i >= 180480) return;
    if (i >= 180224) {                        // w1c: 256 entries
        int j = i - 180224;
        int kk = j >> 7, cc = j & 127;
        g_w1c[kk][cc] = ew1[(kk * 128 + cc) * 257 + 256];
        return;
    }
    if (i >= 163840) {                        // w1abT: [k][c]
        int j = i - 163840;
        int kidx = j >> 7, cc = j & 127;
        g_w1abT[j] = ew1[cc * 257 + kidx] + ew1[cc * 257 + 128 + kidx];
        return;
    }
    float* dst; int j; float val;
    int p, tig, g, cg, kg, ck, row, k;
    if (i < 16384)       { dst = g_pw1a; j = i; }
    else if (i < 32768)  { dst = g_pw1b; j = i - 16384; }
    else if (i < 65536)  { int kk = (i - 32768) >> 14; dst = g_pew2[kk]; j = (i - 32768) & 16383; }
    else if (i < 131072) { int kk = (i - 65536) >> 15; dst = g_pnw1[kk]; j = (i - 65536) & 32767; }
    else                 { int kk = (i - 131072) >> 14; dst = g_pnw2[kk]; j = (i - 131072) & 16383; }
    p = j & 1; tig = (j >> 1) & 3; g = (j >> 3) & 7;
    cg = (j >> 6) & 15; kg = (j >> 10) & 7; ck = j >> 13;
    row = cg * 8 + g;
    k = ck * 64 + kg * 8 + tig + 4 * p;
    if (i < 16384)       val = ew1[(128 + row) * 257 + k];
    else if (i < 32768)  val = ew1[(128 + row) * 257 + 128 + k];
    else if (i < 65536)  val = (ew2 + ((i - 32768) >> 14) * 16384)[row * 128 + k];
    else if (i < 131072) val = (nw1 + ((i - 65536) >> 15) * 32768)[row * 256 + k];
    else                 val = (nw2 + ((i - 131072) >> 14) * 16384)[row * 128 + k];
    dst[j] = f2tf32f(val);
}

// round-0 base: base[b][c] = z0[b] . w1abT[:,c] + b1[c]  (grid 64 x 128)
__global__ void base_kernel(const float* __restrict__ z0,
                            const float* __restrict__ eb1) {
    __shared__ float zs[LLv];
    int b = blockIdx.x, t = threadIdx.x;
    zs[t] = z0[b * LLv + t];
    __syncthreads();
    float acc = eb1[t];
#pragma unroll 8
    for (int k = 0; k < LLv; k++)
        acc = fmaf(zs[k], g_w1abT[k * LLv + t], acc);
    g_base[b * LLv + t] = acc;
}

// ---------------- round-1 per-node projections (tf32 MMA, 64 rows) -----------
#define PJ_SMEM ((64 * 132 + 2 * 4096) * 4)
__global__ __launch_bounds__(256) void proj_kernel(const float* __restrict__ eb1) {
    extern __shared__ float sm[];
    float* Xh  = sm;                 // [64][132]
    float* wb  = sm + 64 * 132;      // 2 x 4096

    int r0 = blockIdx.x * 64, t = threadIdx.x;
    int lane = t & 31, w = t >> 5;
    int g = lane >> 2, tig = lane & 3;
    int wm = w & 1, wn = w >> 1;

#pragma unroll
    for (int i = 0; i < 8; i++) {
        int idx = i * 256 + t;
        int r = idx >> 5, j4 = idx & 31;
        float4 v = ((const float4*)(g_h + (r0 + r) * LLv))[j4];
        float* d = &Xh[r * 132 + j4 * 4];
        d[0] = f2tf32f(v.x); d[1] = f2tf32f(v.y);
        d[2] = f2tf32f(v.z); d[3] = f2tf32f(v.w);
    }

    // 256-thread chunk prefetch: 4096 floats = 256 x 4 float4
    auto pf256 = [&](float* buf, const float* Wp) {
#pragma unroll
        for (int i = 0; i < 4; i++)
            cpa16(buf + (i * 256 + t) * 4, Wp + (i * 256 + t) * 4);
        cpa_commit();
    };
    // warp tile rows wm*32..+32, cols wn*32..+32 (4 col-warps x 2 row-warps)
    auto run4 = [&](float (&c)[2][4][4], const float* Wp) {
        zacc(c);
        pf256(wb, Wp);
        pf256(wb + 4096, Wp + 4096);
#pragma unroll 1
        for (int ci = 0; ci < 4; ci++) {
            if (ci < 3) cpa_wait<1>(); else cpa_wait<0>();
            __syncthreads();
            compute_chunk32<132>(c, Xh + wm * 32 * 132, ci * 32,
                                 wb + (ci & 1) * 4096, lane, wn);
            __syncthreads();
            if (ci + 2 < 4) pf256(wb + (ci & 1) * 4096, Wp + (ci + 2) * 4096);
        }
    };

    float c[2][4][4];
    run4(c, g_pw1a);
#pragma unroll
    for (int mr = 0; mr < 2; mr++)
#pragma unroll
        for (int nf = 0; nf < 4; nf++)
#pragma unroll
            for (int i = 0; i < 4; i++) {
                int row = wm * 32 + mr * 16 + g + (i >> 1) * 8;
                int col = wn * 32 + nf * 8 + 2 * tig + (i & 1);
                g_A[(r0 + row) * LLv + col] = c[mr][nf][i] + eb1[col];
            }
    run4(c, g_pw1b);
#pragma unroll
    for (int mr = 0; mr < 2; mr++)
#pragma unroll
        for (int nf = 0; nf < 4; nf++)
#pragma unroll
            for (int i = 0; i < 4; i++) {
                int row = wm * 32 + mr * 16 + g + (i >> 1) * 8;
                int col = wn * 32 + nf * 8 + 2 * tig + (i & 1);
                g_Bv[(r0 + row) * LLv + col] = c[mr][nf][i];
            }
}

// ---------------- fused per-round node kernel: 32 rows, 128 threads ----------
// smem floats: inp 8320 | xs 4224 | wb 8192 | ea 1024 | tg 1024 | rp 36
#define RK_SMEM ((8320 + 4224 + 8192 + 1024 + 1024 + 36) * 4)
__global__ __launch_bounds__(128) void round_kernel(
    const float* __restrict__ z0,
    const float* __restrict__ eb2,
    const float* __restrict__ nb1,
    const float* __restrict__ lng, const float* __restrict__ lnb,
    const float* __restrict__ nb2,
    int k)
{
    extern __shared__ float sm[];
    float* inp   = sm;                       // [32][260]: [h_tf32 | m_agg_tf32]
    float* xs    = sm + 8320;                // [32][132]
    float* wb    = sm + 8320 + 4224;         // 2 x 4096
    float* es_ea = wb + 8192;                // [1024]
    int*   es_tg = (int*)(es_ea + 1024);     // [1024]
    int*   rp    = (int*)(es_ea + 2048);     // [33]

    const float* pew2 = g_pew2[k];
    const float* pnw1 = g_pnw1[k];
    const float* pnw2 = g_pnw2[k];

    int b = blockIdx.y, q0 = blockIdx.x * 32, t = threadIdx.x;
    int rowbase = (b * NQv + q0) * LLv;
    int lane = t & 31, w = t >> 5;            // 4 warps
    int g = lane >> 2, tig = lane & 3;
    int wn = w;

    if (t < 33) rp[t] = g_rowptr[q0 + t];
    __syncthreads();

    // block-local CSR prefetch
    int e0b = rp[0];
    int cnt = rp[32] - e0b;
    bool insm = (cnt <= 1024);
    if (insm) {
        for (int i = t; i < cnt; i += 128) {
            es_tg[i] = g_csr_tgt[e0b + i];
            es_ea[i] = g_csr_ea[e0b + i];
        }
    }
    __syncthreads();
    const int*   tgp = insm ? es_tg : g_csr_tgt;
    const float* eap = insm ? es_ea : g_csr_ea;
    int ebias = insm ? e0b : 0;

    // ---- stage 1: hid_agg[n] = sum_{e: src=n} relu(A[n]+B[tgt]+ea*w1c) ----
    {
        float4 w1c4 = ((const float4*)&g_w1c[k][0])[lane];
#pragma unroll
        for (int j = 0; j < 8; j++) {
            int r = w * 8 + j;
            float4 a4;
            if (k == 0) a4 = ((const float4*)(g_base + b * LLv))[lane];
            else        a4 = ((const float4*)(g_A + rowbase + r * LLv))[lane];
            float4 acc = make_float4(0.f, 0.f, 0.f, 0.f);
            int e0 = rp[r] - ebias, e1 = rp[r + 1] - ebias;
            if (k == 0) {
                for (int e = e0; e < e1; e++) {
                    float ea = eap[e];
                    acc.x += fmaxf(fmaf(ea, w1c4.x, a4.x), 0.f);
                    acc.y += fmaxf(fmaf(ea, w1c4.y, a4.y), 0.f);
                    acc.z += fmaxf(fmaf(ea, w1c4.z, a4.z), 0.f);
                    acc.w += fmaxf(fmaf(ea, w1c4.w, a4.w), 0.f);
                }
            } else {
                for (int e = e0; e < e1; e++) {
                    float ea = eap[e];
                    int tg = tgp[e];
                    float4 bv = ((const float4*)(g_Bv + (b * NQv + tg) * LLv))[lane];
                    acc.x += fmaxf(fmaf(ea, w1c4.x, a4.x + bv.x), 0.f);
                    acc.y += fmaxf(fmaf(ea, w1c4.y, a4.y + bv.y), 0.f);
                    acc.z += fmaxf(fmaf(ea, w1c4.z, a4.z + bv.z), 0.f);
                    acc.w += fmaxf(fmaf(ea, w1c4.w, a4.w + bv.w), 0.f);
                }
            }
            float* d = &xs[r * 132 + lane * 4];
            d[0] = f2tf32f(acc.x); d[1] = f2tf32f(acc.y);
            d[2] = f2tf32f(acc.z); d[3] = f2tf32f(acc.w);
        }
    }

    float c[2][4][4];

    // ---- GEMM1: m_agg = hid_agg @ W2^T + deg*b2 ----
    run_gemm<132>(c, xs, pew2, 4, wb, t, lane, wn);
#pragma unroll
    for (int mr = 0; mr < 2; mr++)
#pragma unroll
        for (int nf = 0; nf < 4; nf++)
#pragma unroll
            for (int i = 0; i < 4; i++) {
                int row = mr * 16 + g + (i >> 1) * 8;
                int col = wn * 32 + nf * 8 + 2 * tig + (i & 1);
                float dg = (float)(rp[row + 1] - rp[row]);
                inp[row * 260 + 128 + col] = f2tf32f(c[mr][nf][i] + dg * eb2[col]);
            }
    // h rows (rounded) into inp cols 0..127
#pragma unroll
    for (int i = 0; i < 8; i++) {
        int idx = i * 128 + t;                 // 1024 float4 over 32x128
        int r = idx >> 5, j4 = idx & 31;
        float4 v = (k == 0) ? ((const float4*)(z0 + b * LLv))[j4]
                            : ((const float4*)(g_h + rowbase + r * LLv))[j4];
        float* d = &inp[r * 260 + j4 * 4];
        d[0] = f2tf32f(v.x); d[1] = f2tf32f(v.y);
        d[2] = f2tf32f(v.z); d[3] = f2tf32f(v.w);
    }

    // ---- GEMM2: x = [h|m_agg] @ nw1^T (K=256) ----
    run_gemm<260>(c, inp, pnw1, 8, wb, t, lane, wn);
#pragma unroll
    for (int mr = 0; mr < 2; mr++)
#pragma unroll
        for (int nf = 0; nf < 4; nf++)
#pragma unroll
            for (int i = 0; i < 4; i++) {
                int row = mr * 16 + g + (i >> 1) * 8;
                int col = wn * 32 + nf * 8 + 2 * tig + (i & 1);
                xs[row * 132 + col] = fmaxf(c[mr][nf][i] + nb1[col], 0.f);
            }
    __syncthreads();

    // ---- LayerNorm (fp32 stats), write tf32-rounded ----
#pragma unroll
    for (int j = 0; j < 8; j++) {
        int q = w * 8 + j;
        float v0 = xs[q * 132 + lane],      v1 = xs[q * 132 + lane + 32];
        float v2 = xs[q * 132 + lane + 64], v3 = xs[q * 132 + lane + 96];
        float s = v0 + v1 + v2 + v3;
#pragma unroll
        for (int o = 16; o; o >>= 1) s += __shfl_xor_sync(0xffffffffu, s, o);
        float mu = s * (1.f / 128.f);
        float d0 = v0 - mu, d1 = v1 - mu, d2 = v2 - mu, d3 = v3 - mu;
        float s2 = d0 * d0 + d1 * d1 + d2 * d2 + d3 * d3;
#pragma unroll
        for (int o = 16; o; o >>= 1) s2 += __shfl_xor_sync(0xffffffffu, s2, o);
        float rstd = rsqrtf(s2 * (1.f / 128.f) + 1e-5f);
        xs[q * 132 + lane]      = f2tf32f(d0 * rstd * lng[lane]      + lnb[lane]);
        xs[q * 132 + lane + 32] = f2tf32f(d1 * rstd * lng[lane + 32] + lnb[lane + 32]);
        xs[q * 132 + lane + 64] = f2tf32f(d2 * rstd * lng[lane + 64] + lnb[lane + 64]);
        xs[q * 132 + lane + 96] = f2tf32f(d3 * rstd * lng[lane + 96] + lnb[lane + 96]);
    }

    // ---- GEMM3: h = xs @ nw2^T + nb2 + h ----
    run_gemm<132>(c, xs, pnw2, 4, wb, t, lane, wn);
#pragma unroll
    for (int mr = 0; mr < 2; mr++)
#pragma unroll
        for (int nf = 0; nf < 4; nf++)
#pragma unroll
            for (int i = 0; i < 4; i++) {
                int row = mr * 16 + g + (i >> 1) * 8;
                int col = wn * 32 + nf * 8 + 2 * tig + (i & 1);
                float res = (k == 0) ? z0[b * LLv + col]
                                     : g_h[rowbase + row * LLv + col];
                g_h[rowbase + row * LLv + col] = res + c[mr][nf][i] + nb2[col];
            }
}

// ---------------- final mean over nodes --------------------------------------
__global__ void mean_kernel(float* __restrict__ out) {
    int b = blockIdx.x, t = threadIdx.x;   // 512 threads
    int l = t & 127, seg = t >> 7;
    const float* p = g_h + (b * NQv + seg * 256) * LLv + l;
    float s = 0.f;
#pragma unroll 8
    for (int q = 0; q < 256; q++) s += p[q * LLv];
    __shared__ float red[4][LLv];
    red[seg][l] = s;
    __syncthreads();
    if (seg == 0)
        out[b * LLv + l] =
            (red[0][l] + red[1][l] + red[2][l] + red[3][l]) * (1.f / 1024.f);
}

// ---------------- launch ------------------------------------------------------
extern "C" void kernel_launch(void* const* d_in, const int* in_sizes, int n_in,
                              void* d_out, int out_size) {
    const float* z0    = (const float*)d_in[0];
    const void*  eidx  = d_in[1];
    const float* eattr = (const float*)d_in[2];
    const float* ew1 = (const float*)d_in[4];
    const float* eb1 = (const float*)d_in[5];
    const float* ew2 = (const float*)d_in[6];
    const float* eb2 = (const float*)d_in[7];
    const float* nw1 = (const float*)d_in[8];
    const float* nb1 = (const float*)d_in[9];
    const float* lng = (const float*)d_in[10];
    const float* lnb = (const float*)d_in[11];
    const float* nw2 = (const float*)d_in[12];
    const float* nb2 = (const float*)d_in[13];
    float* out = (float*)d_out;

    cudaFuncSetAttribute(round_kernel,
        cudaFuncAttributeMaxDynamicSharedMemorySize, RK_SMEM);
    cudaFuncSetAttribute(proj_kernel,
        cudaFuncAttributeMaxDynamicSharedMemorySize, PJ_SMEM);

    setup_kernel<<<1, 1024>>>(eidx);
    repack_kernel<<<705, 256>>>(ew1, ew2, nw1, nw2);
    fill_kernel<<<NQv / 8, 256>>>(eattr);

    base_kernel<<<BB, 128>>>(z0, eb1);
    round_kernel<<<dim3(NQv / 32, BB), 128, RK_SMEM>>>(
        z0, eb2, nb1, lng, lnb, nb2, 0);

    proj_kernel<<<BB * NQv / 64, 256, PJ_SMEM>>>(eb1 + 128);
    round_kernel<<<dim3(NQv / 32, BB), 128, RK_SMEM>>>(
        z0, eb2 + LLv, nb1 + LLv,
        lng + LLv, lnb + LLv, nb2 + LLv, 1);

    mean_kernel<<<BB, 512>>>(out);
}